// round 4
// baseline (speedup 1.0000x reference)
#include <cuda_runtime.h>

// Problem shape (fixed by the reference)
#define Bn 8
#define Tn 1024
#define Cn 768
#define Hn 8
#define Dn 96
#define Mn (Bn*Tn)      // 8192 rows
#define N3 (3*Cn)       // 2304

// Scratch (allocation-free rule: __device__ globals)
__device__ float g_qkv[(size_t)Mn * N3];   // [B*T, 3C]  (q|k|v interleaved per row)
__device__ float g_y[(size_t)Mn * Cn];     // [B*T, C]   attention output

// ---------------------------------------------------------------------------
// Generic 128x128 tiled SGEMM with bias:  Cout[M,N] = A[M,K] @ W[K,N] + bias[N]
// 256 threads (16x16), 8x8 per-thread micro-tile with split fragments
// (cols/rows at t*4 and 64+t*4) so all smem fragment loads are conflict-free
// LDS.128.  BK = 16.
// ---------------------------------------------------------------------------
__global__ __launch_bounds__(256)
void gemm_bias_128x128(const float* __restrict__ A,
                       const float* __restrict__ W,
                       const float* __restrict__ bias,
                       float* __restrict__ Cout,
                       int Ndim, int Kdim)
{
    __shared__ float As[16 * 132];   // A tile, transposed: As[k][m], padded row
    __shared__ float Bs[16 * 128];   // B tile: Bs[k][n]

    const int tid = threadIdx.x;
    const int tx = tid & 15, ty = tid >> 4;
    const int tx4 = tx * 4, ty4 = ty * 4;
    const int m0 = blockIdx.y * 128;
    const int n0 = blockIdx.x * 128;

    float acc[8][8];
#pragma unroll
    for (int r = 0; r < 8; r++)
#pragma unroll
        for (int c = 0; c < 8; c++) acc[r][c] = 0.f;

    for (int kt = 0; kt < Kdim; kt += 16) {
        __syncthreads();
        // Load A tile [128 m][16 k] -> transposed smem (float4 along k)
#pragma unroll
        for (int i = tid; i < 512; i += 256) {
            int row = i >> 2, kq = (i & 3) << 2;
            float4 v = *(const float4*)(A + (size_t)(m0 + row) * Kdim + kt + kq);
            As[(kq + 0) * 132 + row] = v.x;
            As[(kq + 1) * 132 + row] = v.y;
            As[(kq + 2) * 132 + row] = v.z;
            As[(kq + 3) * 132 + row] = v.w;
        }
        // Load B tile [16 k][128 n]
#pragma unroll
        for (int i = tid; i < 512; i += 256) {
            int k = i >> 5, n = (i & 31) << 2;
            *(float4*)(Bs + k * 128 + n) =
                *(const float4*)(W + (size_t)(kt + k) * Ndim + n0 + n);
        }
        __syncthreads();

#pragma unroll
        for (int kk = 0; kk < 16; kk++) {
            float4 a0 = *(const float4*)(As + kk * 132 + ty4);
            float4 a1 = *(const float4*)(As + kk * 132 + 64 + ty4);
            float4 b0 = *(const float4*)(Bs + kk * 128 + tx4);
            float4 b1 = *(const float4*)(Bs + kk * 128 + 64 + tx4);
            float a[8]  = {a0.x, a0.y, a0.z, a0.w, a1.x, a1.y, a1.z, a1.w};
            float bb[8] = {b0.x, b0.y, b0.z, b0.w, b1.x, b1.y, b1.z, b1.w};
#pragma unroll
            for (int r = 0; r < 8; r++)
#pragma unroll
                for (int c = 0; c < 8; c++)
                    acc[r][c] += a[r] * bb[c];
        }
    }

    float4 bv0 = *(const float4*)(bias + n0 + tx4);
    float4 bv1 = *(const float4*)(bias + n0 + 64 + tx4);
#pragma unroll
    for (int r = 0; r < 8; r++) {
        int m = m0 + ((r < 4) ? (ty4 + r) : (64 + ty4 + r - 4));
        float4 o0 = make_float4(acc[r][0] + bv0.x, acc[r][1] + bv0.y,
                                acc[r][2] + bv0.z, acc[r][3] + bv0.w);
        float4 o1 = make_float4(acc[r][4] + bv1.x, acc[r][5] + bv1.y,
                                acc[r][6] + bv1.z, acc[r][7] + bv1.w);
        *(float4*)(Cout + (size_t)m * Ndim + n0 + tx4)      = o0;
        *(float4*)(Cout + (size_t)m * Ndim + n0 + 64 + tx4) = o1;
    }
}

// ---------------------------------------------------------------------------
// Flash-style causal attention, fp32.
// grid = (T/128 q-tiles, B*H).  256 threads (16x16).
// Streams K/V tiles of 128 keys; online softmax; only tiles kt <= qt visited.
// smem: Qs[96][132] (transposed, pre-scaled), Ks[96][132] (transposed),
//       Vs[128][100], Ps[128][132]  -> 220160 bytes (< 227 KB opt-in).
// ---------------------------------------------------------------------------
#define QP 132
#define VP 100
#define PP 132
#define ATT_SMEM_BYTES ((96*QP + 96*QP + 128*VP + 128*PP) * 4)

extern __shared__ float sm_att[];

__global__ __launch_bounds__(256)
void attention_kernel()
{
    float* Qs = sm_att;
    float* Ks = Qs + 96 * QP;
    float* Vs = Ks + 96 * QP;
    float* Ps = Vs + 128 * VP;

    const int tid = threadIdx.x;
    const int tx = tid & 15, ty = tid >> 4;
    const int tx4 = tx * 4, ty4 = ty * 4;
    const int qt = blockIdx.x;          // q tile 0..7
    const int bh = blockIdx.y;          // 0..63
    const int b = bh >> 3, h = bh & 7;

    const float* qbase = g_qkv + (size_t)b * Tn * N3 + h * Dn;
    const float* kbase = qbase + Cn;
    const float* vbase = qbase + 2 * Cn;

    const float scale = rsqrtf((float)Dn);

    int rows_[8];
#pragma unroll
    for (int r = 0; r < 8; r++)
        rows_[r] = (r < 4) ? (ty4 + r) : (64 + ty4 + r - 4);

    // Load Q tile (pre-scaled by 1/sqrt(D)), transposed: Qs[d][m]
    for (int i = tid; i < 128 * 24; i += 256) {
        int row = i / 24, j = i - row * 24;
        float4 v = *(const float4*)(qbase + (size_t)(qt * 128 + row) * N3 + j * 4);
        Qs[(j * 4 + 0) * QP + row] = v.x * scale;
        Qs[(j * 4 + 1) * QP + row] = v.y * scale;
        Qs[(j * 4 + 2) * QP + row] = v.z * scale;
        Qs[(j * 4 + 3) * QP + row] = v.w * scale;
    }

    // O accumulator: 8 rows x 6 d-cols per thread (cols tx*4..+4 and 64+tx*2..+2)
    float accO[8][6];
#pragma unroll
    for (int r = 0; r < 8; r++)
#pragma unroll
        for (int c = 0; c < 6; c++) accO[r][c] = 0.f;
    float rmax[8], rsum[8];
#pragma unroll
    for (int r = 0; r < 8; r++) { rmax[r] = -1e30f; rsum[r] = 0.f; }

    for (int kt = 0; kt <= qt; kt++) {
        __syncthreads();  // prev PV done (and Q tile visible on first iter)
        // Load K tile transposed Ks[d][n], V tile direct Vs[n][d]
        for (int i = tid; i < 128 * 24; i += 256) {
            int row = i / 24, j = i - row * 24;
            float4 kv = *(const float4*)(kbase + (size_t)(kt * 128 + row) * N3 + j * 4);
            Ks[(j * 4 + 0) * QP + row] = kv.x;
            Ks[(j * 4 + 1) * QP + row] = kv.y;
            Ks[(j * 4 + 2) * QP + row] = kv.z;
            Ks[(j * 4 + 3) * QP + row] = kv.w;
            float4 vv = *(const float4*)(vbase + (size_t)(kt * 128 + row) * N3 + j * 4);
            *(float4*)(Vs + row * VP + j * 4) = vv;
        }
        __syncthreads();

        // S = Q K^T (pre-scaled)
        float s[8][8];
#pragma unroll
        for (int r = 0; r < 8; r++)
#pragma unroll
            for (int c = 0; c < 8; c++) s[r][c] = 0.f;

#pragma unroll 4
        for (int d = 0; d < 96; d++) {
            float4 a0 = *(const float4*)(Qs + d * QP + ty4);
            float4 a1 = *(const float4*)(Qs + d * QP + 64 + ty4);
            float4 b0 = *(const float4*)(Ks + d * QP + tx4);
            float4 b1 = *(const float4*)(Ks + d * QP + 64 + tx4);
            float a[8]  = {a0.x, a0.y, a0.z, a0.w, a1.x, a1.y, a1.z, a1.w};
            float bb[8] = {b0.x, b0.y, b0.z, b0.w, b1.x, b1.y, b1.z, b1.w};
#pragma unroll
            for (int r = 0; r < 8; r++)
#pragma unroll
                for (int c = 0; c < 8; c++)
                    s[r][c] += a[r] * bb[c];
        }

        // Causal mask only on the diagonal tile
        if (kt == qt) {
#pragma unroll
            for (int r = 0; r < 8; r++)
#pragma unroll
                for (int c = 0; c < 8; c++) {
                    int cc = (c < 4) ? (tx4 + c) : (64 + tx4 + c - 4);
                    if (cc > rows_[r]) s[r][c] = -1e30f;
                }
        }

        // Online softmax per row.  Row-group = 16 consecutive lanes of a
        // half-warp (tid = ty*16+tx), so shfl_xor offsets 1..8 reduce it.
#pragma unroll
        for (int r = 0; r < 8; r++) {
            float tmax = s[r][0];
#pragma unroll
            for (int c = 1; c < 8; c++) tmax = fmaxf(tmax, s[r][c]);
#pragma unroll
            for (int off = 1; off < 16; off <<= 1)
                tmax = fmaxf(tmax, __shfl_xor_sync(0xffffffffu, tmax, off));
            float nmax = fmaxf(rmax[r], tmax);
            float corr = __expf(rmax[r] - nmax);  // exactly 0 on first tile
            rmax[r] = nmax;
            float tsum = 0.f;
#pragma unroll
            for (int c = 0; c < 8; c++) {
                s[r][c] = __expf(s[r][c] - nmax);
                tsum += s[r][c];
            }
#pragma unroll
            for (int off = 1; off < 16; off <<= 1)
                tsum += __shfl_xor_sync(0xffffffffu, tsum, off);
            rsum[r] = rsum[r] * corr + tsum;
#pragma unroll
            for (int c = 0; c < 6; c++) accO[r][c] *= corr;
            *(float4*)(Ps + rows_[r] * PP + tx4) =
                make_float4(s[r][0], s[r][1], s[r][2], s[r][3]);
            *(float4*)(Ps + rows_[r] * PP + 64 + tx4) =
                make_float4(s[r][4], s[r][5], s[r][6], s[r][7]);
        }
        __syncthreads();

        // O += P @ V   (P rows broadcast from smem, V conflict-free vector loads)
#pragma unroll 2
        for (int kk = 0; kk < 128; kk++) {
            float4 v0 = *(const float4*)(Vs + kk * VP + tx4);
            float2 v1 = *(const float2*)(Vs + kk * VP + 64 + tx * 2);
            float vv[6] = {v0.x, v0.y, v0.z, v0.w, v1.x, v1.y};
#pragma unroll
            for (int r = 0; r < 8; r++) {
                float p = Ps[rows_[r] * PP + kk];
#pragma unroll
                for (int c = 0; c < 6; c++) accO[r][c] += p * vv[c];
            }
        }
    }

    // Normalize and store y[b, t, h*96 + d]
    float* ybase = g_y + (size_t)b * Tn * Cn + h * Dn;
#pragma unroll
    for (int r = 0; r < 8; r++) {
        float inv = 1.f / rsum[r];
        size_t off = (size_t)(qt * 128 + rows_[r]) * Cn;
        *(float4*)(ybase + off + tx4) =
            make_float4(accO[r][0] * inv, accO[r][1] * inv,
                        accO[r][2] * inv, accO[r][3] * inv);
        *(float2*)(ybase + off + 64 + tx * 2) =
            make_float2(accO[r][4] * inv, accO[r][5] * inv);
    }
}

// ---------------------------------------------------------------------------
// Launch: QKV GEMM -> attention -> projection GEMM.  All on the capture
// stream; no sync, no alloc.
// ---------------------------------------------------------------------------
extern "C" void kernel_launch(void* const* d_in, const int* in_sizes, int n_in,
                              void* d_out, int out_size)
{
    const float* x      = (const float*)d_in[0];
    const float* W_attn = (const float*)d_in[1];
    const float* b_attn = (const float*)d_in[2];
    const float* W_proj = (const float*)d_in[3];
    const float* b_proj = (const float*)d_in[4];
    float* out = (float*)d_out;

    float* qkv = nullptr;
    float* y   = nullptr;
    cudaGetSymbolAddress((void**)&qkv, g_qkv);
    cudaGetSymbolAddress((void**)&y,   g_y);

    cudaFuncSetAttribute(attention_kernel,
                         cudaFuncAttributeMaxDynamicSharedMemorySize,
                         ATT_SMEM_BYTES);

    dim3 blk(256);
    // 1) qkv = x @ W_attn + b_attn          [8192, 2304]
    gemm_bias_128x128<<<dim3(N3 / 128, Mn / 128), blk>>>(x, W_attn, b_attn, qkv,
                                                         N3, Cn);
    // 2) y = causal_attention(q, k, v)      [8192, 768]
    attention_kernel<<<dim3(Tn / 128, Bn * Hn), blk, ATT_SMEM_BYTES>>>();
    // 3) out = y @ W_proj + b_proj          [8192, 768]
    gemm_bias_128x128<<<dim3(Cn / 128, Mn / 128), blk>>>(y, W_proj, b_proj, out,
                                                         Cn, Cn);
}

// round 6
// speedup vs baseline: 1.4100x; 1.4100x over previous
#include <cuda_runtime.h>
#include <cuda_bf16.h>
#include <cstdint>

// Problem shape (fixed by the reference)
#define Bn 8
#define Tn 1024
#define Cn 768
#define Hn 8
#define Dn 96
#define Mn (Bn*Tn)      // 8192 rows
#define N3 (3*Cn)       // 2304
#define Kd 768

// ---------------------------------------------------------------------------
// Scratch (allocation-free rule: __device__ globals)
// ---------------------------------------------------------------------------
__device__ float g_qkv[(size_t)Mn * N3];   // [B*T, 3C]
__device__ float g_y[(size_t)Mn * Cn];     // [B*T, C] attention output
__device__ __nv_bfloat16 g_xh[(size_t)Mn * Cn], g_xl[(size_t)Mn * Cn];
__device__ __nv_bfloat16 g_yh[(size_t)Mn * Cn], g_yl[(size_t)Mn * Cn];
__device__ __nv_bfloat16 g_WaTh[(size_t)N3 * Cn], g_WaTl[(size_t)N3 * Cn]; // W_attn^T [2304,768]
__device__ __nv_bfloat16 g_WpTh[(size_t)Cn * Cn], g_WpTl[(size_t)Cn * Cn]; // W_proj^T [768,768]

// ---------------------------------------------------------------------------
// Portable tensor-core primitives (sm_80+, legal at .target sm_103)
// ---------------------------------------------------------------------------
__device__ __forceinline__ uint32_t smem_u32(const void* p) {
    uint32_t a;
    asm("{ .reg .u64 t; cvta.to.shared.u64 t, %1; cvt.u32.u64 %0, t; }" : "=r"(a) : "l"(p));
    return a;
}
__device__ __forceinline__ void ldsm_x4(uint32_t* r, uint32_t addr) {
    asm volatile("ldmatrix.sync.aligned.m8n8.x4.shared.b16 {%0,%1,%2,%3}, [%4];"
                 : "=r"(r[0]), "=r"(r[1]), "=r"(r[2]), "=r"(r[3]) : "r"(addr));
}
__device__ __forceinline__ void ldsm_x2(uint32_t* r, uint32_t addr) {
    asm volatile("ldmatrix.sync.aligned.m8n8.x2.shared.b16 {%0,%1}, [%2];"
                 : "=r"(r[0]), "=r"(r[1]) : "r"(addr));
}
__device__ __forceinline__ void mma_16816(float* c, const uint32_t* a, const uint32_t* b) {
    asm volatile("mma.sync.aligned.m16n8k16.row.col.f32.bf16.bf16.f32 "
                 "{%0,%1,%2,%3}, {%4,%5,%6,%7}, {%8,%9}, {%0,%1,%2,%3};"
                 : "+f"(c[0]), "+f"(c[1]), "+f"(c[2]), "+f"(c[3])
                 : "r"(a[0]), "r"(a[1]), "r"(a[2]), "r"(a[3]), "r"(b[0]), "r"(b[1]));
}
__device__ __forceinline__ void cp16(uint32_t saddr, const void* g) {
    asm volatile("cp.async.cg.shared.global [%0], [%1], 16;" :: "r"(saddr), "l"(g));
}
#define CP_COMMIT() asm volatile("cp.async.commit_group;" ::: "memory")

// ---------------------------------------------------------------------------
// Conversion kernels: fp32 -> (bf16 hi, bf16 lo) split
// ---------------------------------------------------------------------------
__global__ __launch_bounds__(256)
void split_fp32(const float* __restrict__ src, __nv_bfloat16* __restrict__ hi,
                __nv_bfloat16* __restrict__ lo, int n4)
{
    int i = blockIdx.x * blockDim.x + threadIdx.x;
    if (i >= n4) return;
    float4 v = ((const float4*)src)[i];
    __nv_bfloat16 h0 = __float2bfloat16(v.x), h1 = __float2bfloat16(v.y);
    __nv_bfloat16 h2 = __float2bfloat16(v.z), h3 = __float2bfloat16(v.w);
    __nv_bfloat16 l0 = __float2bfloat16(v.x - __bfloat162float(h0));
    __nv_bfloat16 l1 = __float2bfloat16(v.y - __bfloat162float(h1));
    __nv_bfloat16 l2 = __float2bfloat16(v.z - __bfloat162float(h2));
    __nv_bfloat16 l3 = __float2bfloat16(v.w - __bfloat162float(h3));
    __nv_bfloat162* H = (__nv_bfloat162*)hi;
    __nv_bfloat162* L = (__nv_bfloat162*)lo;
    __nv_bfloat162 p;
    p.x = h0; p.y = h1; H[i * 2] = p;
    p.x = h2; p.y = h3; H[i * 2 + 1] = p;
    p.x = l0; p.y = l1; L[i * 2] = p;
    p.x = l2; p.y = l3; L[i * 2 + 1] = p;
}

// W[K=768, Ndim] row-major -> transposed split bf16 [Ndim, 768]
__global__ __launch_bounds__(256)
void transpose_split(const float* __restrict__ W, __nv_bfloat16* __restrict__ Th,
                     __nv_bfloat16* __restrict__ Tl, int Ndim)
{
    __shared__ float t[32][33];
    int tx = threadIdx.x & 31, ty = threadIdx.x >> 5;
    int n0 = blockIdx.x * 32, k0 = blockIdx.y * 32;
#pragma unroll
    for (int i = 0; i < 32; i += 8)
        t[ty + i][tx] = W[(size_t)(k0 + ty + i) * Ndim + n0 + tx];
    __syncthreads();
#pragma unroll
    for (int i = 0; i < 32; i += 8) {
        float v = t[tx][ty + i];
        __nv_bfloat16 h = __float2bfloat16(v);
        size_t o = (size_t)(n0 + ty + i) * Kd + k0 + tx;
        Th[o] = h;
        Tl[o] = __float2bfloat16(v - __bfloat162float(h));
    }
}

// ---------------------------------------------------------------------------
// Tensor-core GEMM via mma.sync (bf16 3-term split, fp32 accum):
//   Cout[M, Ndim] = (Ah+Al)[M,768] @ (BTh+BTl)[Ndim,768]^T + bias
// CTA 128x128, 8 warps of 64x32.  K-tiles of 32 double-buffered via cp.async.
// Smem rows padded to 80B: chunk index row*5 mod 8 is a permutation ->
// conflict-free ldmatrix.
// ---------------------------------------------------------------------------
#define ROWB 80
#define TILEB (128 * ROWB)          // 10240 B per 128x32-bf16 tile
#define STAGEB (4 * TILEB)          // Ah | Al | Bh | Bl
#define GEMM_SMEM_DYN (2 * STAGEB)  // 81920 B

extern __shared__ float sm_dyn[];

__device__ __forceinline__ void gemm_issue_stage(
    const __nv_bfloat16* const* tp, uint32_t sdst, int kt, int tid)
{
#pragma unroll
    for (int i = 0; i < 8; i++) {
        int id = i * 256 + tid;
        int tile = id >> 9;
        int r = (id >> 2) & 127;
        int c = id & 3;
        const __nv_bfloat16* g = tp[tile] + (size_t)r * Kd + kt * 32 + c * 8;
        cp16(sdst + tile * TILEB + r * ROWB + c * 16, g);
    }
    CP_COMMIT();
}

__global__ __launch_bounds__(256, 1)
void tensor_gemm(const __nv_bfloat16* __restrict__ Ah, const __nv_bfloat16* __restrict__ Al,
                 const __nv_bfloat16* __restrict__ BTh, const __nv_bfloat16* __restrict__ BTl,
                 const float* __restrict__ bias, float* __restrict__ Cout, int Ndim)
{
    const int tid = threadIdx.x;
    const int wid = tid >> 5, lane = tid & 31;
    const int m0 = blockIdx.y * 128;
    const int n0 = blockIdx.x * 128;
    const int wm = (wid >> 2) * 64;        // warp m-offset in tile
    const int wn = (wid & 3) * 32;         // warp n-offset in tile

    const uint32_t sbase = smem_u32(sm_dyn);

    const __nv_bfloat16* tp[4] = {
        Ah  + (size_t)m0 * Kd,
        Al  + (size_t)m0 * Kd,
        BTh + (size_t)n0 * Kd,
        BTl + (size_t)n0 * Kd
    };

    float acc[4][4][4];
#pragma unroll
    for (int mf = 0; mf < 4; mf++)
#pragma unroll
        for (int nf = 0; nf < 4; nf++)
#pragma unroll
            for (int j = 0; j < 4; j++) acc[mf][nf][j] = 0.f;

    // ldmatrix lane-address components
    const int arow = wm + (lane & 15);
    const int akb  = (lane >> 4) << 3;          // 0 or 8 halves
    const int brow = wn + (lane & 7);
    const int bkb  = ((lane >> 3) & 1) << 3;

    gemm_issue_stage(tp, sbase, 0, tid);

    for (int kt = 0; kt < 24; kt++) {
        const int st = kt & 1;
        if (kt + 1 < 24) {
            gemm_issue_stage(tp, sbase + (st ^ 1) * STAGEB, kt + 1, tid);
            asm volatile("cp.async.wait_group 1;" ::: "memory");
        } else {
            asm volatile("cp.async.wait_group 0;" ::: "memory");
        }
        __syncthreads();

        const uint32_t Ahb = sbase + st * STAGEB;
        const uint32_t Alb = Ahb + TILEB;
        const uint32_t Bhb = Ahb + 2 * TILEB;
        const uint32_t Blb = Ahb + 3 * TILEB;

#pragma unroll
        for (int kf = 0; kf < 2; kf++) {
            const int kb = kf * 16;
            uint32_t ah[4][4], al[4][4], bh[4][2], bl[4][2];
#pragma unroll
            for (int mf = 0; mf < 4; mf++) {
                uint32_t off = (uint32_t)(arow + mf * 16) * ROWB + (kb + akb) * 2;
                ldsm_x4(ah[mf], Ahb + off);
                ldsm_x4(al[mf], Alb + off);
            }
#pragma unroll
            for (int nf = 0; nf < 4; nf++) {
                uint32_t off = (uint32_t)(brow + nf * 8) * ROWB + (kb + bkb) * 2;
                ldsm_x2(bh[nf], Bhb + off);
                ldsm_x2(bl[nf], Blb + off);
            }
#pragma unroll
            for (int mf = 0; mf < 4; mf++)
#pragma unroll
                for (int nf = 0; nf < 4; nf++) {
                    mma_16816(acc[mf][nf], ah[mf], bh[nf]);
                    mma_16816(acc[mf][nf], ah[mf], bl[nf]);
                    mma_16816(acc[mf][nf], al[mf], bh[nf]);
                }
        }
        __syncthreads();
    }

    // Epilogue: fragment layout c0,c1 -> (row, col), (row, col+1); c2,c3 -> row+8
    const int mrow = m0 + wm + (lane >> 2);
    const int ncol = n0 + wn + (lane & 3) * 2;
#pragma unroll
    for (int mf = 0; mf < 4; mf++)
#pragma unroll
        for (int nf = 0; nf < 4; nf++) {
            int r = mrow + mf * 16, c = ncol + nf * 8;
            float b0 = bias[c], b1 = bias[c + 1];
            *(float2*)(Cout + (size_t)r * Ndim + c) =
                make_float2(acc[mf][nf][0] + b0, acc[mf][nf][1] + b1);
            *(float2*)(Cout + (size_t)(r + 8) * Ndim + c) =
                make_float2(acc[mf][nf][2] + b0, acc[mf][nf][3] + b1);
        }
}

// ---------------------------------------------------------------------------
// Flash-style causal attention, fp32 (unchanged from R4 passing kernel).
// grid = (T/128 q-tiles, B*H).  256 threads (16x16).
// ---------------------------------------------------------------------------
#define QP 132
#define VP 100
#define PP 132
#define ATT_SMEM_BYTES ((96*QP + 96*QP + 128*VP + 128*PP) * 4)

__global__ __launch_bounds__(256)
void attention_kernel()
{
    float* Qs = sm_dyn;
    float* Ks = Qs + 96 * QP;
    float* Vs = Ks + 96 * QP;
    float* Ps = Vs + 128 * VP;

    const int tid = threadIdx.x;
    const int tx = tid & 15, ty = tid >> 4;
    const int tx4 = tx * 4, ty4 = ty * 4;
    const int qt = blockIdx.x;
    const int bh = blockIdx.y;
    const int b = bh >> 3, h = bh & 7;

    const float* qbase = g_qkv + (size_t)b * Tn * N3 + h * Dn;
    const float* kbase = qbase + Cn;
    const float* vbase = qbase + 2 * Cn;

    const float scale = rsqrtf((float)Dn);

    int rows_[8];
#pragma unroll
    for (int r = 0; r < 8; r++)
        rows_[r] = (r < 4) ? (ty4 + r) : (64 + ty4 + r - 4);

    for (int i = tid; i < 128 * 24; i += 256) {
        int row = i / 24, j = i - row * 24;
        float4 v = *(const float4*)(qbase + (size_t)(qt * 128 + row) * N3 + j * 4);
        Qs[(j * 4 + 0) * QP + row] = v.x * scale;
        Qs[(j * 4 + 1) * QP + row] = v.y * scale;
        Qs[(j * 4 + 2) * QP + row] = v.z * scale;
        Qs[(j * 4 + 3) * QP + row] = v.w * scale;
    }

    float accO[8][6];
#pragma unroll
    for (int r = 0; r < 8; r++)
#pragma unroll
        for (int c = 0; c < 6; c++) accO[r][c] = 0.f;
    float rmax[8], rsum[8];
#pragma unroll
    for (int r = 0; r < 8; r++) { rmax[r] = -1e30f; rsum[r] = 0.f; }

    for (int kt = 0; kt <= qt; kt++) {
        __syncthreads();
        for (int i = tid; i < 128 * 24; i += 256) {
            int row = i / 24, j = i - row * 24;
            float4 kv = *(const float4*)(kbase + (size_t)(kt * 128 + row) * N3 + j * 4);
            Ks[(j * 4 + 0) * QP + row] = kv.x;
            Ks[(j * 4 + 1) * QP + row] = kv.y;
            Ks[(j * 4 + 2) * QP + row] = kv.z;
            Ks[(j * 4 + 3) * QP + row] = kv.w;
            float4 vv = *(const float4*)(vbase + (size_t)(kt * 128 + row) * N3 + j * 4);
            *(float4*)(Vs + row * VP + j * 4) = vv;
        }
        __syncthreads();

        float s[8][8];
#pragma unroll
        for (int r = 0; r < 8; r++)
#pragma unroll
            for (int c = 0; c < 8; c++) s[r][c] = 0.f;

#pragma unroll 4
        for (int d = 0; d < 96; d++) {
            float4 a0 = *(const float4*)(Qs + d * QP + ty4);
            float4 a1 = *(const float4*)(Qs + d * QP + 64 + ty4);
            float4 b0 = *(const float4*)(Ks + d * QP + tx4);
            float4 b1 = *(const float4*)(Ks + d * QP + 64 + tx4);
            float a[8]  = {a0.x, a0.y, a0.z, a0.w, a1.x, a1.y, a1.z, a1.w};
            float bb[8] = {b0.x, b0.y, b0.z, b0.w, b1.x, b1.y, b1.z, b1.w};
#pragma unroll
            for (int r = 0; r < 8; r++)
#pragma unroll
                for (int c = 0; c < 8; c++)
                    s[r][c] += a[r] * bb[c];
        }

        if (kt == qt) {
#pragma unroll
            for (int r = 0; r < 8; r++)
#pragma unroll
                for (int c = 0; c < 8; c++) {
                    int cc = (c < 4) ? (tx4 + c) : (64 + tx4 + c - 4);
                    if (cc > rows_[r]) s[r][c] = -1e30f;
                }
        }

#pragma unroll
        for (int r = 0; r < 8; r++) {
            float tmax = s[r][0];
#pragma unroll
            for (int c = 1; c < 8; c++) tmax = fmaxf(tmax, s[r][c]);
#pragma unroll
            for (int off = 1; off < 16; off <<= 1)
                tmax = fmaxf(tmax, __shfl_xor_sync(0xffffffffu, tmax, off));
            float nmax = fmaxf(rmax[r], tmax);
            float corr = __expf(rmax[r] - nmax);
            rmax[r] = nmax;
            float tsum = 0.f;
#pragma unroll
            for (int c = 0; c < 8; c++) {
                s[r][c] = __expf(s[r][c] - nmax);
                tsum += s[r][c];
            }
#pragma unroll
            for (int off = 1; off < 16; off <<= 1)
                tsum += __shfl_xor_sync(0xffffffffu, tsum, off);
            rsum[r] = rsum[r] * corr + tsum;
#pragma unroll
            for (int c = 0; c < 6; c++) accO[r][c] *= corr;
            *(float4*)(Ps + rows_[r] * PP + tx4) =
                make_float4(s[r][0], s[r][1], s[r][2], s[r][3]);
            *(float4*)(Ps + rows_[r] * PP + 64 + tx4) =
                make_float4(s[r][4], s[r][5], s[r][6], s[r][7]);
        }
        __syncthreads();

#pragma unroll 2
        for (int kk = 0; kk < 128; kk++) {
            float4 v0 = *(const float4*)(Vs + kk * VP + tx4);
            float2 v1 = *(const float2*)(Vs + kk * VP + 64 + tx * 2);
            float vv[6] = {v0.x, v0.y, v0.z, v0.w, v1.x, v1.y};
#pragma unroll
            for (int r = 0; r < 8; r++) {
                float p = Ps[rows_[r] * PP + kk];
#pragma unroll
                for (int c = 0; c < 6; c++) accO[r][c] += p * vv[c];
            }
        }
    }

    float* ybase = g_y + (size_t)b * Tn * Cn + h * Dn;
#pragma unroll
    for (int r = 0; r < 8; r++) {
        float inv = 1.f / rsum[r];
        size_t off = (size_t)(qt * 128 + rows_[r]) * Cn;
        *(float4*)(ybase + off + tx4) =
            make_float4(accO[r][0] * inv, accO[r][1] * inv,
                        accO[r][2] * inv, accO[r][3] * inv);
        *(float2*)(ybase + off + 64 + tx * 2) =
            make_float2(accO[r][4] * inv, accO[r][5] * inv);
    }
}

// ---------------------------------------------------------------------------
// Launch pipeline
// ---------------------------------------------------------------------------
extern "C" void kernel_launch(void* const* d_in, const int* in_sizes, int n_in,
                              void* d_out, int out_size)
{
    const float* x      = (const float*)d_in[0];
    const float* W_attn = (const float*)d_in[1];
    const float* b_attn = (const float*)d_in[2];
    const float* W_proj = (const float*)d_in[3];
    const float* b_proj = (const float*)d_in[4];
    float* out = (float*)d_out;

    float *qkv, *y;
    __nv_bfloat16 *xh, *xl, *yh, *yl, *wath, *watl, *wpth, *wptl;
    cudaGetSymbolAddress((void**)&qkv,  g_qkv);
    cudaGetSymbolAddress((void**)&y,    g_y);
    cudaGetSymbolAddress((void**)&xh,   g_xh);
    cudaGetSymbolAddress((void**)&xl,   g_xl);
    cudaGetSymbolAddress((void**)&yh,   g_yh);
    cudaGetSymbolAddress((void**)&yl,   g_yl);
    cudaGetSymbolAddress((void**)&wath, g_WaTh);
    cudaGetSymbolAddress((void**)&watl, g_WaTl);
    cudaGetSymbolAddress((void**)&wpth, g_WpTh);
    cudaGetSymbolAddress((void**)&wptl, g_WpTl);

    cudaFuncSetAttribute(attention_kernel,
                         cudaFuncAttributeMaxDynamicSharedMemorySize, ATT_SMEM_BYTES);
    cudaFuncSetAttribute(tensor_gemm,
                         cudaFuncAttributeMaxDynamicSharedMemorySize, GEMM_SMEM_DYN);

    const int n4x = (Mn * Cn) / 4;
    split_fp32<<<(n4x + 255) / 256, 256>>>(x, xh, xl, n4x);
    transpose_split<<<dim3(N3 / 32, Kd / 32), 256>>>(W_attn, wath, watl, N3);
    transpose_split<<<dim3(Cn / 32, Kd / 32), 256>>>(W_proj, wpth, wptl, Cn);

    // 1) qkv = x @ W_attn + b_attn   [8192, 2304]
    tensor_gemm<<<dim3(N3 / 128, Mn / 128), 256, GEMM_SMEM_DYN>>>(
        xh, xl, wath, watl, b_attn, qkv, N3);

    // 2) y = causal_attention(q, k, v)
    attention_kernel<<<dim3(Tn / 128, Bn * Hn), 256, ATT_SMEM_BYTES>>>();

    // 3) out = y @ W_proj + b_proj   [8192, 768]
    split_fp32<<<(n4x + 255) / 256, 256>>>(y, yh, yl, n4x);
    tensor_gemm<<<dim3(Cn / 128, Mn / 128), 256, GEMM_SMEM_DYN>>>(
        yh, yl, wpth, wptl, b_proj, out, Cn);
}

// round 7
// speedup vs baseline: 1.4116x; 1.0011x over previous
#include <cuda_runtime.h>
#include <cuda_bf16.h>
#include <cstdint>

// Problem shape (fixed by the reference)
#define Bn 8
#define Tn 1024
#define Cn 768
#define Hn 8
#define Dn 96
#define Mn (Bn*Tn)      // 8192 rows
#define N3 (3*Cn)       // 2304
#define Kd 768

// ---------------------------------------------------------------------------
// Scratch (allocation-free rule: __device__ globals)
// ---------------------------------------------------------------------------
__device__ float g_qkv[(size_t)Mn * N3];   // [B*T, 3C]
__device__ float g_y[(size_t)Mn * Cn];     // [B*T, C] attention output
__device__ __nv_bfloat16 g_xh[(size_t)Mn * Cn], g_xl[(size_t)Mn * Cn];
__device__ __nv_bfloat16 g_yh[(size_t)Mn * Cn], g_yl[(size_t)Mn * Cn];
__device__ __nv_bfloat16 g_WaTh[(size_t)N3 * Cn], g_WaTl[(size_t)N3 * Cn]; // W_attn^T [2304,768]
__device__ __nv_bfloat16 g_WpTh[(size_t)Cn * Cn], g_WpTl[(size_t)Cn * Cn]; // W_proj^T [768,768]

// ---------------------------------------------------------------------------
// Portable tensor-core primitives (sm_80+, legal at .target sm_103)
// ---------------------------------------------------------------------------
__device__ __forceinline__ uint32_t smem_u32(const void* p) {
    uint32_t a;
    asm("{ .reg .u64 t; cvta.to.shared.u64 t, %1; cvt.u32.u64 %0, t; }" : "=r"(a) : "l"(p));
    return a;
}
__device__ __forceinline__ void ldsm_x4(uint32_t* r, uint32_t addr) {
    asm volatile("ldmatrix.sync.aligned.m8n8.x4.shared.b16 {%0,%1,%2,%3}, [%4];"
                 : "=r"(r[0]), "=r"(r[1]), "=r"(r[2]), "=r"(r[3]) : "r"(addr));
}
__device__ __forceinline__ void ldsm_x2(uint32_t* r, uint32_t addr) {
    asm volatile("ldmatrix.sync.aligned.m8n8.x2.shared.b16 {%0,%1}, [%2];"
                 : "=r"(r[0]), "=r"(r[1]) : "r"(addr));
}
__device__ __forceinline__ void mma_16816(float* c, const uint32_t* a, const uint32_t* b) {
    asm volatile("mma.sync.aligned.m16n8k16.row.col.f32.bf16.bf16.f32 "
                 "{%0,%1,%2,%3}, {%4,%5,%6,%7}, {%8,%9}, {%0,%1,%2,%3};"
                 : "+f"(c[0]), "+f"(c[1]), "+f"(c[2]), "+f"(c[3])
                 : "r"(a[0]), "r"(a[1]), "r"(a[2]), "r"(a[3]), "r"(b[0]), "r"(b[1]));
}
__device__ __forceinline__ void cp16(uint32_t saddr, const void* g) {
    asm volatile("cp.async.cg.shared.global [%0], [%1], 16;" :: "r"(saddr), "l"(g));
}
#define CP_COMMIT() asm volatile("cp.async.commit_group;" ::: "memory")

// ---------------------------------------------------------------------------
// Conversion kernels: fp32 -> (bf16 hi, bf16 lo) split
// ---------------------------------------------------------------------------
__global__ __launch_bounds__(256)
void split_fp32(const float* __restrict__ src, __nv_bfloat16* __restrict__ hi,
                __nv_bfloat16* __restrict__ lo, int n4)
{
    int i = blockIdx.x * blockDim.x + threadIdx.x;
    if (i >= n4) return;
    float4 v = ((const float4*)src)[i];
    __nv_bfloat16 h0 = __float2bfloat16(v.x), h1 = __float2bfloat16(v.y);
    __nv_bfloat16 h2 = __float2bfloat16(v.z), h3 = __float2bfloat16(v.w);
    __nv_bfloat16 l0 = __float2bfloat16(v.x - __bfloat162float(h0));
    __nv_bfloat16 l1 = __float2bfloat16(v.y - __bfloat162float(h1));
    __nv_bfloat16 l2 = __float2bfloat16(v.z - __bfloat162float(h2));
    __nv_bfloat16 l3 = __float2bfloat16(v.w - __bfloat162float(h3));
    __nv_bfloat162* H = (__nv_bfloat162*)hi;
    __nv_bfloat162* L = (__nv_bfloat162*)lo;
    __nv_bfloat162 p;
    p.x = h0; p.y = h1; H[i * 2] = p;
    p.x = h2; p.y = h3; H[i * 2 + 1] = p;
    p.x = l0; p.y = l1; L[i * 2] = p;
    p.x = l2; p.y = l3; L[i * 2 + 1] = p;
}

// W[K=768, Ndim] row-major -> transposed split bf16 [Ndim, 768]
__global__ __launch_bounds__(256)
void transpose_split(const float* __restrict__ W, __nv_bfloat16* __restrict__ Th,
                     __nv_bfloat16* __restrict__ Tl, int Ndim)
{
    __shared__ float t[32][33];
    int tx = threadIdx.x & 31, ty = threadIdx.x >> 5;
    int n0 = blockIdx.x * 32, k0 = blockIdx.y * 32;
#pragma unroll
    for (int i = 0; i < 32; i += 8)
        t[ty + i][tx] = W[(size_t)(k0 + ty + i) * Ndim + n0 + tx];
    __syncthreads();
#pragma unroll
    for (int i = 0; i < 32; i += 8) {
        float v = t[tx][ty + i];
        __nv_bfloat16 h = __float2bfloat16(v);
        size_t o = (size_t)(n0 + ty + i) * Kd + k0 + tx;
        Th[o] = h;
        Tl[o] = __float2bfloat16(v - __bfloat162float(h));
    }
}

// ---------------------------------------------------------------------------
// Tensor-core GEMM via mma.sync (bf16 3-term split, fp32 accum):
//   Cout[M, Ndim] = (Ah+Al)[M,768] @ (BTh+BTl)[Ndim,768]^T + bias
// CTA 128x128, 8 warps of 64x32.  K-tiles of 32 double-buffered via cp.async.
// Smem rows padded to 80B: chunk index row*5 mod 8 is a permutation ->
// conflict-free ldmatrix.
// ---------------------------------------------------------------------------
#define ROWB 80
#define TILEB (128 * ROWB)          // 10240 B per 128x32-bf16 tile
#define STAGEB (4 * TILEB)          // Ah | Al | Bh | Bl
#define GEMM_SMEM_DYN (2 * STAGEB)  // 81920 B

extern __shared__ float sm_dyn[];

__device__ __forceinline__ void gemm_issue_stage(
    const __nv_bfloat16* const* tp, uint32_t sdst, int kt, int tid)
{
#pragma unroll
    for (int i = 0; i < 8; i++) {
        int id = i * 256 + tid;
        int tile = id >> 9;
        int r = (id >> 2) & 127;
        int c = id & 3;
        const __nv_bfloat16* g = tp[tile] + (size_t)r * Kd + kt * 32 + c * 8;
        cp16(sdst + tile * TILEB + r * ROWB + c * 16, g);
    }
    CP_COMMIT();
}

__global__ __launch_bounds__(256, 1)
void tensor_gemm(const __nv_bfloat16* __restrict__ Ah, const __nv_bfloat16* __restrict__ Al,
                 const __nv_bfloat16* __restrict__ BTh, const __nv_bfloat16* __restrict__ BTl,
                 const float* __restrict__ bias, float* __restrict__ Cout, int Ndim)
{
    const int tid = threadIdx.x;
    const int wid = tid >> 5, lane = tid & 31;
    const int m0 = blockIdx.y * 128;
    const int n0 = blockIdx.x * 128;
    const int wm = (wid >> 2) * 64;        // warp m-offset in tile
    const int wn = (wid & 3) * 32;         // warp n-offset in tile

    const uint32_t sbase = smem_u32(sm_dyn);

    const __nv_bfloat16* tp[4] = {
        Ah  + (size_t)m0 * Kd,
        Al  + (size_t)m0 * Kd,
        BTh + (size_t)n0 * Kd,
        BTl + (size_t)n0 * Kd
    };

    float acc[4][4][4];
#pragma unroll
    for (int mf = 0; mf < 4; mf++)
#pragma unroll
        for (int nf = 0; nf < 4; nf++)
#pragma unroll
            for (int j = 0; j < 4; j++) acc[mf][nf][j] = 0.f;

    // ldmatrix lane-address components
    const int arow = wm + (lane & 15);
    const int akb  = (lane >> 4) << 3;          // 0 or 8 halves
    const int brow = wn + (lane & 7);
    const int bkb  = ((lane >> 3) & 1) << 3;

    gemm_issue_stage(tp, sbase, 0, tid);

    for (int kt = 0; kt < 24; kt++) {
        const int st = kt & 1;
        if (kt + 1 < 24) {
            gemm_issue_stage(tp, sbase + (st ^ 1) * STAGEB, kt + 1, tid);
            asm volatile("cp.async.wait_group 1;" ::: "memory");
        } else {
            asm volatile("cp.async.wait_group 0;" ::: "memory");
        }
        __syncthreads();

        const uint32_t Ahb = sbase + st * STAGEB;
        const uint32_t Alb = Ahb + TILEB;
        const uint32_t Bhb = Ahb + 2 * TILEB;
        const uint32_t Blb = Ahb + 3 * TILEB;

#pragma unroll
        for (int kf = 0; kf < 2; kf++) {
            const int kb = kf * 16;
            uint32_t ah[4][4], al[4][4], bh[4][2], bl[4][2];
#pragma unroll
            for (int mf = 0; mf < 4; mf++) {
                uint32_t off = (uint32_t)(arow + mf * 16) * ROWB + (kb + akb) * 2;
                ldsm_x4(ah[mf], Ahb + off);
                ldsm_x4(al[mf], Alb + off);
            }
#pragma unroll
            for (int nf = 0; nf < 4; nf++) {
                uint32_t off = (uint32_t)(brow + nf * 8) * ROWB + (kb + bkb) * 2;
                ldsm_x2(bh[nf], Bhb + off);
                ldsm_x2(bl[nf], Blb + off);
            }
#pragma unroll
            for (int mf = 0; mf < 4; mf++)
#pragma unroll
                for (int nf = 0; nf < 4; nf++) {
                    mma_16816(acc[mf][nf], ah[mf], bh[nf]);
                    mma_16816(acc[mf][nf], ah[mf], bl[nf]);
                    mma_16816(acc[mf][nf], al[mf], bh[nf]);
                }
        }
        __syncthreads();
    }

    // Epilogue: fragment layout c0,c1 -> (row, col), (row, col+1); c2,c3 -> row+8
    const int mrow = m0 + wm + (lane >> 2);
    const int ncol = n0 + wn + (lane & 3) * 2;
#pragma unroll
    for (int mf = 0; mf < 4; mf++)
#pragma unroll
        for (int nf = 0; nf < 4; nf++) {
            int r = mrow + mf * 16, c = ncol + nf * 8;
            float b0 = bias[c], b1 = bias[c + 1];
            *(float2*)(Cout + (size_t)r * Ndim + c) =
                make_float2(acc[mf][nf][0] + b0, acc[mf][nf][1] + b1);
            *(float2*)(Cout + (size_t)(r + 8) * Ndim + c) =
                make_float2(acc[mf][nf][2] + b0, acc[mf][nf][3] + b1);
        }
}

// ---------------------------------------------------------------------------
// Flash-style causal attention, fp32 (unchanged from R4 passing kernel).
// grid = (T/128 q-tiles, B*H).  256 threads (16x16).
// ---------------------------------------------------------------------------
#define QP 132
#define VP 100
#define PP 132
#define ATT_SMEM_BYTES ((96*QP + 96*QP + 128*VP + 128*PP) * 4)

__global__ __launch_bounds__(256)
void attention_kernel()
{
    float* Qs = sm_dyn;
    float* Ks = Qs + 96 * QP;
    float* Vs = Ks + 96 * QP;
    float* Ps = Vs + 128 * VP;

    const int tid = threadIdx.x;
    const int tx = tid & 15, ty = tid >> 4;
    const int tx4 = tx * 4, ty4 = ty * 4;
    const int qt = blockIdx.x;
    const int bh = blockIdx.y;
    const int b = bh >> 3, h = bh & 7;

    const float* qbase = g_qkv + (size_t)b * Tn * N3 + h * Dn;
    const float* kbase = qbase + Cn;
    const float* vbase = qbase + 2 * Cn;

    const float scale = rsqrtf((float)Dn);

    int rows_[8];
#pragma unroll
    for (int r = 0; r < 8; r++)
        rows_[r] = (r < 4) ? (ty4 + r) : (64 + ty4 + r - 4);

    for (int i = tid; i < 128 * 24; i += 256) {
        int row = i / 24, j = i - row * 24;
        float4 v = *(const float4*)(qbase + (size_t)(qt * 128 + row) * N3 + j * 4);
        Qs[(j * 4 + 0) * QP + row] = v.x * scale;
        Qs[(j * 4 + 1) * QP + row] = v.y * scale;
        Qs[(j * 4 + 2) * QP + row] = v.z * scale;
        Qs[(j * 4 + 3) * QP + row] = v.w * scale;
    }

    float accO[8][6];
#pragma unroll
    for (int r = 0; r < 8; r++)
#pragma unroll
        for (int c = 0; c < 6; c++) accO[r][c] = 0.f;
    float rmax[8], rsum[8];
#pragma unroll
    for (int r = 0; r < 8; r++) { rmax[r] = -1e30f; rsum[r] = 0.f; }

    for (int kt = 0; kt <= qt; kt++) {
        __syncthreads();
        for (int i = tid; i < 128 * 24; i += 256) {
            int row = i / 24, j = i - row * 24;
            float4 kv = *(const float4*)(kbase + (size_t)(kt * 128 + row) * N3 + j * 4);
            Ks[(j * 4 + 0) * QP + row] = kv.x;
            Ks[(j * 4 + 1) * QP + row] = kv.y;
            Ks[(j * 4 + 2) * QP + row] = kv.z;
            Ks[(j * 4 + 3) * QP + row] = kv.w;
            float4 vv = *(const float4*)(vbase + (size_t)(kt * 128 + row) * N3 + j * 4);
            *(float4*)(Vs + row * VP + j * 4) = vv;
        }
        __syncthreads();

        float s[8][8];
#pragma unroll
        for (int r = 0; r < 8; r++)
#pragma unroll
            for (int c = 0; c < 8; c++) s[r][c] = 0.f;

#pragma unroll 4
        for (int d = 0; d < 96; d++) {
            float4 a0 = *(const float4*)(Qs + d * QP + ty4);
            float4 a1 = *(const float4*)(Qs + d * QP + 64 + ty4);
            float4 b0 = *(const float4*)(Ks + d * QP + tx4);
            float4 b1 = *(const float4*)(Ks + d * QP + 64 + tx4);
            float a[8]  = {a0.x, a0.y, a0.z, a0.w, a1.x, a1.y, a1.z, a1.w};
            float bb[8] = {b0.x, b0.y, b0.z, b0.w, b1.x, b1.y, b1.z, b1.w};
#pragma unroll
            for (int r = 0; r < 8; r++)
#pragma unroll
                for (int c = 0; c < 8; c++)
                    s[r][c] += a[r] * bb[c];
        }

        if (kt == qt) {
#pragma unroll
            for (int r = 0; r < 8; r++)
#pragma unroll
                for (int c = 0; c < 8; c++) {
                    int cc = (c < 4) ? (tx4 + c) : (64 + tx4 + c - 4);
                    if (cc > rows_[r]) s[r][c] = -1e30f;
                }
        }

#pragma unroll
        for (int r = 0; r < 8; r++) {
            float tmax = s[r][0];
#pragma unroll
            for (int c = 1; c < 8; c++) tmax = fmaxf(tmax, s[r][c]);
#pragma unroll
            for (int off = 1; off < 16; off <<= 1)
                tmax = fmaxf(tmax, __shfl_xor_sync(0xffffffffu, tmax, off));
            float nmax = fmaxf(rmax[r], tmax);
            float corr = __expf(rmax[r] - nmax);
            rmax[r] = nmax;
            float tsum = 0.f;
#pragma unroll
            for (int c = 0; c < 8; c++) {
                s[r][c] = __expf(s[r][c] - nmax);
                tsum += s[r][c];
            }
#pragma unroll
            for (int off = 1; off < 16; off <<= 1)
                tsum += __shfl_xor_sync(0xffffffffu, tsum, off);
            rsum[r] = rsum[r] * corr + tsum;
#pragma unroll
            for (int c = 0; c < 6; c++) accO[r][c] *= corr;
            *(float4*)(Ps + rows_[r] * PP + tx4) =
                make_float4(s[r][0], s[r][1], s[r][2], s[r][3]);
            *(float4*)(Ps + rows_[r] * PP + 64 + tx4) =
                make_float4(s[r][4], s[r][5], s[r][6], s[r][7]);
        }
        __syncthreads();

#pragma unroll 2
        for (int kk = 0; kk < 128; kk++) {
            float4 v0 = *(const float4*)(Vs + kk * VP + tx4);
            float2 v1 = *(const float2*)(Vs + kk * VP + 64 + tx * 2);
            float vv[6] = {v0.x, v0.y, v0.z, v0.w, v1.x, v1.y};
#pragma unroll
            for (int r = 0; r < 8; r++) {
                float p = Ps[rows_[r] * PP + kk];
#pragma unroll
                for (int c = 0; c < 6; c++) accO[r][c] += p * vv[c];
            }
        }
    }

    float* ybase = g_y + (size_t)b * Tn * Cn + h * Dn;
#pragma unroll
    for (int r = 0; r < 8; r++) {
        float inv = 1.f / rsum[r];
        size_t off = (size_t)(qt * 128 + rows_[r]) * Cn;
        *(float4*)(ybase + off + tx4) =
            make_float4(accO[r][0] * inv, accO[r][1] * inv,
                        accO[r][2] * inv, accO[r][3] * inv);
        *(float2*)(ybase + off + 64 + tx * 2) =
            make_float2(accO[r][4] * inv, accO[r][5] * inv);
    }
}

// ---------------------------------------------------------------------------
// Launch pipeline
// ---------------------------------------------------------------------------
extern "C" void kernel_launch(void* const* d_in, const int* in_sizes, int n_in,
                              void* d_out, int out_size)
{
    const float* x      = (const float*)d_in[0];
    const float* W_attn = (const float*)d_in[1];
    const float* b_attn = (const float*)d_in[2];
    const float* W_proj = (const float*)d_in[3];
    const float* b_proj = (const float*)d_in[4];
    float* out = (float*)d_out;

    float *qkv, *y;
    __nv_bfloat16 *xh, *xl, *yh, *yl, *wath, *watl, *wpth, *wptl;
    cudaGetSymbolAddress((void**)&qkv,  g_qkv);
    cudaGetSymbolAddress((void**)&y,    g_y);
    cudaGetSymbolAddress((void**)&xh,   g_xh);
    cudaGetSymbolAddress((void**)&xl,   g_xl);
    cudaGetSymbolAddress((void**)&yh,   g_yh);
    cudaGetSymbolAddress((void**)&yl,   g_yl);
    cudaGetSymbolAddress((void**)&wath, g_WaTh);
    cudaGetSymbolAddress((void**)&watl, g_WaTl);
    cudaGetSymbolAddress((void**)&wpth, g_WpTh);
    cudaGetSymbolAddress((void**)&wptl, g_WpTl);

    cudaFuncSetAttribute(attention_kernel,
                         cudaFuncAttributeMaxDynamicSharedMemorySize, ATT_SMEM_BYTES);
    cudaFuncSetAttribute(tensor_gemm,
                         cudaFuncAttributeMaxDynamicSharedMemorySize, GEMM_SMEM_DYN);

    const int n4x = (Mn * Cn) / 4;
    split_fp32<<<(n4x + 255) / 256, 256>>>(x, xh, xl, n4x);
    transpose_split<<<dim3(N3 / 32, Kd / 32), 256>>>(W_attn, wath, watl, N3);
    transpose_split<<<dim3(Cn / 32, Kd / 32), 256>>>(W_proj, wpth, wptl, Cn);

    // 1) qkv = x @ W_attn + b_attn   [8192, 2304]
    tensor_gemm<<<dim3(N3 / 128, Mn / 128), 256, GEMM_SMEM_DYN>>>(
        xh, xl, wath, watl, b_attn, qkv, N3);

    // 2) y = causal_attention(q, k, v)
    attention_kernel<<<dim3(Tn / 128, Bn * Hn), 256, ATT_SMEM_BYTES>>>();

    // 3) out = y @ W_proj + b_proj   [8192, 768]
    split_fp32<<<(n4x + 255) / 256, 256>>>(y, yh, yl, n4x);
    tensor_gemm<<<dim3(Cn / 128, Mn / 128), 256, GEMM_SMEM_DYN>>>(
        yh, yl, wpth, wptl, b_proj, out, Cn);
}

// round 8
// speedup vs baseline: 2.0438x; 1.4479x over previous
#include <cuda_runtime.h>
#include <cuda_bf16.h>
#include <cstdint>

// Problem shape (fixed by the reference)
#define Bn 8
#define Tn 1024
#define Cn 768
#define Hn 8
#define Dn 96
#define Mn (Bn*Tn)      // 8192 rows
#define N3 (3*Cn)       // 2304
#define Kd 768

// ---------------------------------------------------------------------------
// Scratch (allocation-free rule: __device__ globals)
// ---------------------------------------------------------------------------
__device__ float g_qkv[(size_t)Mn * N3];   // [B*T, 3C]
__device__ __nv_bfloat16 g_xh[(size_t)Mn * Cn], g_xl[(size_t)Mn * Cn];
__device__ __nv_bfloat16 g_yh[(size_t)Mn * Cn], g_yl[(size_t)Mn * Cn];
__device__ __nv_bfloat16 g_WaTh[(size_t)N3 * Cn], g_WaTl[(size_t)N3 * Cn];
__device__ __nv_bfloat16 g_WpTh[(size_t)Cn * Cn], g_WpTl[(size_t)Cn * Cn];
// Attention operands: [bh][1024][96] for Q,K; [bh][96][1024] for V^T
#define AQE ((size_t)Bn * Hn * Tn * Dn)
__device__ __nv_bfloat16 g_Qh[AQE], g_Ql[AQE];
__device__ __nv_bfloat16 g_Kh[AQE], g_Kl[AQE];
__device__ __nv_bfloat16 g_VTh[AQE], g_VTl[AQE];

// ---------------------------------------------------------------------------
// Portable tensor-core primitives (sm_80+, legal at .target sm_103)
// ---------------------------------------------------------------------------
__device__ __forceinline__ uint32_t smem_u32(const void* p) {
    uint32_t a;
    asm("{ .reg .u64 t; cvta.to.shared.u64 t, %1; cvt.u32.u64 %0, t; }" : "=r"(a) : "l"(p));
    return a;
}
__device__ __forceinline__ void ldsm_x4(uint32_t* r, uint32_t addr) {
    asm volatile("ldmatrix.sync.aligned.m8n8.x4.shared.b16 {%0,%1,%2,%3}, [%4];"
                 : "=r"(r[0]), "=r"(r[1]), "=r"(r[2]), "=r"(r[3]) : "r"(addr));
}
__device__ __forceinline__ void ldsm_x2(uint32_t* r, uint32_t addr) {
    asm volatile("ldmatrix.sync.aligned.m8n8.x2.shared.b16 {%0,%1}, [%2];"
                 : "=r"(r[0]), "=r"(r[1]) : "r"(addr));
}
__device__ __forceinline__ void mma_16816(float* c, const uint32_t* a, const uint32_t* b) {
    asm volatile("mma.sync.aligned.m16n8k16.row.col.f32.bf16.bf16.f32 "
                 "{%0,%1,%2,%3}, {%4,%5,%6,%7}, {%8,%9}, {%0,%1,%2,%3};"
                 : "+f"(c[0]), "+f"(c[1]), "+f"(c[2]), "+f"(c[3])
                 : "r"(a[0]), "r"(a[1]), "r"(a[2]), "r"(a[3]), "r"(b[0]), "r"(b[1]));
}
__device__ __forceinline__ void cp16(uint32_t saddr, const void* g) {
    asm volatile("cp.async.cg.shared.global [%0], [%1], 16;" :: "r"(saddr), "l"(g));
}
#define CP_COMMIT() asm volatile("cp.async.commit_group;" ::: "memory")
#define CP_WAIT0()  asm volatile("cp.async.wait_group 0;" ::: "memory")

// Split a float pair into bf16x2 hi + lo words
__device__ __forceinline__ void split2w(float a, float b, uint32_t& h, uint32_t& l) {
    __nv_bfloat16 ha = __float2bfloat16(a), hb = __float2bfloat16(b);
    __nv_bfloat162 H; H.x = ha; H.y = hb;
    __nv_bfloat162 L;
    L.x = __float2bfloat16(a - __bfloat162float(ha));
    L.y = __float2bfloat16(b - __bfloat162float(hb));
    h = *(uint32_t*)&H; l = *(uint32_t*)&L;
}

// ---------------------------------------------------------------------------
// Conversion kernels
// ---------------------------------------------------------------------------
__global__ __launch_bounds__(256)
void split_fp32(const float* __restrict__ src, __nv_bfloat16* __restrict__ hi,
                __nv_bfloat16* __restrict__ lo, int n4)
{
    int i = blockIdx.x * blockDim.x + threadIdx.x;
    if (i >= n4) return;
    float4 v = ((const float4*)src)[i];
    uint32_t h0, l0, h1, l1;
    split2w(v.x, v.y, h0, l0);
    split2w(v.z, v.w, h1, l1);
    ((uint32_t*)hi)[i * 2] = h0; ((uint32_t*)hi)[i * 2 + 1] = h1;
    ((uint32_t*)lo)[i * 2] = l0; ((uint32_t*)lo)[i * 2 + 1] = l1;
}

// W[K=768, Ndim] row-major -> transposed split bf16 [Ndim, 768]
__global__ __launch_bounds__(256)
void transpose_split(const float* __restrict__ W, __nv_bfloat16* __restrict__ Th,
                     __nv_bfloat16* __restrict__ Tl, int Ndim)
{
    __shared__ float t[32][33];
    int tx = threadIdx.x & 31, ty = threadIdx.x >> 5;
    int n0 = blockIdx.x * 32, k0 = blockIdx.y * 32;
#pragma unroll
    for (int i = 0; i < 32; i += 8)
        t[ty + i][tx] = W[(size_t)(k0 + ty + i) * Ndim + n0 + tx];
    __syncthreads();
#pragma unroll
    for (int i = 0; i < 32; i += 8) {
        float v = t[tx][ty + i];
        __nv_bfloat16 h = __float2bfloat16(v);
        size_t o = (size_t)(n0 + ty + i) * Kd + k0 + tx;
        Th[o] = h;
        Tl[o] = __float2bfloat16(v - __bfloat162float(h));
    }
}

// qkv fp32 -> attention operands: Qh/Ql (pre-scaled), Kh/Kl, VTh/VTl (transposed)
__global__ __launch_bounds__(256)
void attn_prep()
{
    __shared__ float vs[128][101];
    const int tt = blockIdx.x;     // token tile 0..63 (global over 8192)
    const int h  = blockIdx.y;     // head
    const int tid = threadIdx.x;
    const int b = tt >> 3;
    const int bh = b * Hn + h;
    const int tloc = (tt & 7) * 128;      // token offset within this bh
    const float* base = g_qkv + (size_t)tt * 128 * N3 + h * Dn;
    const float scale = rsqrtf((float)Dn);

    uint32_t* Qh2 = (uint32_t*)(g_Qh + ((size_t)bh * Tn + tloc) * Dn);
    uint32_t* Ql2 = (uint32_t*)(g_Ql + ((size_t)bh * Tn + tloc) * Dn);
    uint32_t* Kh2 = (uint32_t*)(g_Kh + ((size_t)bh * Tn + tloc) * Dn);
    uint32_t* Kl2 = (uint32_t*)(g_Kl + ((size_t)bh * Tn + tloc) * Dn);

    for (int i = tid; i < 128 * 24; i += 256) {
        int row = i / 24, j = i - row * 24;
        const float* p = base + (size_t)row * N3 + j * 4;
        float4 q = *(const float4*)(p);
        float4 k = *(const float4*)(p + Cn);
        float4 v = *(const float4*)(p + 2 * Cn);
        uint32_t h0, l0, h1, l1;
        split2w(q.x * scale, q.y * scale, h0, l0);
        split2w(q.z * scale, q.w * scale, h1, l1);
        int o = row * 48 + j * 2;
        Qh2[o] = h0; Qh2[o + 1] = h1; Ql2[o] = l0; Ql2[o + 1] = l1;
        split2w(k.x, k.y, h0, l0);
        split2w(k.z, k.w, h1, l1);
        Kh2[o] = h0; Kh2[o + 1] = h1; Kl2[o] = l0; Kl2[o + 1] = l1;
        vs[row][j * 4 + 0] = v.x; vs[row][j * 4 + 1] = v.y;
        vs[row][j * 4 + 2] = v.z; vs[row][j * 4 + 3] = v.w;
    }
    __syncthreads();
    for (int i = tid; i < 96 * 64; i += 256) {
        int d = i >> 6, tp = i & 63;
        uint32_t hh, ll;
        split2w(vs[2 * tp][d], vs[2 * tp + 1][d], hh, ll);
        size_t o = (((size_t)bh * Dn + d) * Tn + tloc) / 2 + tp;
        ((uint32_t*)g_VTh)[o] = hh;
        ((uint32_t*)g_VTl)[o] = ll;
    }
}

// ---------------------------------------------------------------------------
// Tensor-core GEMM via mma.sync (bf16 3-term split) — unchanged from R7
// ---------------------------------------------------------------------------
#define ROWB 80
#define TILEB (128 * ROWB)
#define STAGEB (4 * TILEB)
#define GEMM_SMEM_DYN (2 * STAGEB)

extern __shared__ float sm_dyn[];

__device__ __forceinline__ void gemm_issue_stage(
    const __nv_bfloat16* const* tp, uint32_t sdst, int kt, int tid)
{
#pragma unroll
    for (int i = 0; i < 8; i++) {
        int id = i * 256 + tid;
        int tile = id >> 9;
        int r = (id >> 2) & 127;
        int c = id & 3;
        const __nv_bfloat16* g = tp[tile] + (size_t)r * Kd + kt * 32 + c * 8;
        cp16(sdst + tile * TILEB + r * ROWB + c * 16, g);
    }
    CP_COMMIT();
}

__global__ __launch_bounds__(256, 1)
void tensor_gemm(const __nv_bfloat16* __restrict__ Ah, const __nv_bfloat16* __restrict__ Al,
                 const __nv_bfloat16* __restrict__ BTh, const __nv_bfloat16* __restrict__ BTl,
                 const float* __restrict__ bias, float* __restrict__ Cout, int Ndim)
{
    const int tid = threadIdx.x;
    const int wid = tid >> 5, lane = tid & 31;
    const int m0 = blockIdx.y * 128;
    const int n0 = blockIdx.x * 128;
    const int wm = (wid >> 2) * 64;
    const int wn = (wid & 3) * 32;

    const uint32_t sbase = smem_u32(sm_dyn);

    const __nv_bfloat16* tp[4] = {
        Ah  + (size_t)m0 * Kd, Al  + (size_t)m0 * Kd,
        BTh + (size_t)n0 * Kd, BTl + (size_t)n0 * Kd
    };

    float acc[4][4][4];
#pragma unroll
    for (int mf = 0; mf < 4; mf++)
#pragma unroll
        for (int nf = 0; nf < 4; nf++)
#pragma unroll
            for (int j = 0; j < 4; j++) acc[mf][nf][j] = 0.f;

    const int arow = wm + (lane & 15);
    const int akb  = (lane >> 4) << 3;
    const int brow = wn + (lane & 7);
    const int bkb  = ((lane >> 3) & 1) << 3;

    gemm_issue_stage(tp, sbase, 0, tid);

    for (int kt = 0; kt < 24; kt++) {
        const int st = kt & 1;
        if (kt + 1 < 24) {
            gemm_issue_stage(tp, sbase + (st ^ 1) * STAGEB, kt + 1, tid);
            asm volatile("cp.async.wait_group 1;" ::: "memory");
        } else {
            CP_WAIT0();
        }
        __syncthreads();

        const uint32_t Ahb = sbase + st * STAGEB;
        const uint32_t Alb = Ahb + TILEB;
        const uint32_t Bhb = Ahb + 2 * TILEB;
        const uint32_t Blb = Ahb + 3 * TILEB;

#pragma unroll
        for (int kf = 0; kf < 2; kf++) {
            const int kb = kf * 16;
            uint32_t ah[4][4], al[4][4], bh[4][2], bl[4][2];
#pragma unroll
            for (int mf = 0; mf < 4; mf++) {
                uint32_t off = (uint32_t)(arow + mf * 16) * ROWB + (kb + akb) * 2;
                ldsm_x4(ah[mf], Ahb + off);
                ldsm_x4(al[mf], Alb + off);
            }
#pragma unroll
            for (int nf = 0; nf < 4; nf++) {
                uint32_t off = (uint32_t)(brow + nf * 8) * ROWB + (kb + bkb) * 2;
                ldsm_x2(bh[nf], Bhb + off);
                ldsm_x2(bl[nf], Blb + off);
            }
#pragma unroll
            for (int mf = 0; mf < 4; mf++)
#pragma unroll
                for (int nf = 0; nf < 4; nf++) {
                    mma_16816(acc[mf][nf], ah[mf], bh[nf]);
                    mma_16816(acc[mf][nf], ah[mf], bl[nf]);
                    mma_16816(acc[mf][nf], al[mf], bh[nf]);
                }
        }
        __syncthreads();
    }

    const int mrow = m0 + wm + (lane >> 2);
    const int ncol = n0 + wn + (lane & 3) * 2;
#pragma unroll
    for (int mf = 0; mf < 4; mf++)
#pragma unroll
        for (int nf = 0; nf < 4; nf++) {
            int r = mrow + mf * 16, c = ncol + nf * 8;
            float b0 = bias[c], b1 = bias[c + 1];
            *(float2*)(Cout + (size_t)r * Ndim + c) =
                make_float2(acc[mf][nf][0] + b0, acc[mf][nf][1] + b1);
            *(float2*)(Cout + (size_t)(r + 8) * Ndim + c) =
                make_float2(acc[mf][nf][2] + b0, acc[mf][nf][3] + b1);
        }
}

// ---------------------------------------------------------------------------
// Tensor-core flash attention.  grid = (8 q-tiles, 64 bh), 256 threads.
// Warp w owns q-rows [w*16, w*16+16).  S and PV use bf16 3-term split.
// P fragments repacked from S accumulators in registers.
// Smem rows: Q/K padded to 208B (13x16B), VT to 272B (17x16B) -> ldmatrix
// conflict-free (13r mod 8, 17r mod 8 are permutations).
// ---------------------------------------------------------------------------
#define SQp 208
#define SVp 272
#define OFF_QH 0
#define OFF_QL (128 * SQp)
#define OFF_KH (2 * 128 * SQp)
#define OFF_KL (3 * 128 * SQp)
#define OFF_VH (4 * 128 * SQp)
#define OFF_VL (4 * 128 * SQp + 96 * SVp)
#define ATT_SMEM (4 * 128 * SQp + 2 * 96 * SVp)   // 158720 B

__global__ __launch_bounds__(256, 1)
void attention_mma()
{
    const int tid = threadIdx.x, lane = tid & 31, w = tid >> 5;
    const int qt = blockIdx.x, bh = blockIdx.y;
    const int b = bh >> 3, h = bh & 7;
    const uint32_t sb = smem_u32(sm_dyn);

    const __nv_bfloat16* gQh = g_Qh + ((size_t)bh * Tn + qt * 128) * Dn;
    const __nv_bfloat16* gQl = g_Ql + ((size_t)bh * Tn + qt * 128) * Dn;
    const __nv_bfloat16* gKh = g_Kh + (size_t)bh * Tn * Dn;
    const __nv_bfloat16* gKl = g_Kl + (size_t)bh * Tn * Dn;
    const __nv_bfloat16* gVh = g_VTh + (size_t)bh * Dn * Tn;
    const __nv_bfloat16* gVl = g_VTl + (size_t)bh * Dn * Tn;

    // Q tile: 128 x 96 bf16 (12 16B chunks/row), hi+lo
    for (int i = tid; i < 128 * 12; i += 256) {
        int r = i / 12, c = i - r * 12;
        cp16(sb + OFF_QH + r * SQp + c * 16, gQh + r * Dn + c * 8);
        cp16(sb + OFF_QL + r * SQp + c * 16, gQl + r * Dn + c * 8);
    }
    CP_COMMIT();

    float oacc[12][4];
#pragma unroll
    for (int i = 0; i < 12; i++)
#pragma unroll
        for (int j = 0; j < 4; j++) oacc[i][j] = 0.f;
    float m0 = -1e30f, m1 = -1e30f, l0 = 0.f, l1 = 0.f;

    for (int kt = 0; kt <= qt; kt++) {
        if (kt) __syncthreads();   // prev compute done before overwrite
        const __nv_bfloat16* kh = gKh + (size_t)kt * 128 * Dn;
        const __nv_bfloat16* kl = gKl + (size_t)kt * 128 * Dn;
        for (int i = tid; i < 128 * 12; i += 256) {
            int r = i / 12, c = i - r * 12;
            cp16(sb + OFF_KH + r * SQp + c * 16, kh + r * Dn + c * 8);
            cp16(sb + OFF_KL + r * SQp + c * 16, kl + r * Dn + c * 8);
        }
        for (int i = tid; i < 96 * 16; i += 256) {
            int d = i >> 4, c = i & 15;
            cp16(sb + OFF_VH + d * SVp + c * 16, gVh + (size_t)d * Tn + kt * 128 + c * 8);
            cp16(sb + OFF_VL + d * SVp + c * 16, gVl + (size_t)d * Tn + kt * 128 + c * 8);
        }
        CP_COMMIT();
        CP_WAIT0();
        __syncthreads();

        // ---- S = Q K^T (3-term split) ----
        float sacc[16][4];
#pragma unroll
        for (int i = 0; i < 16; i++)
#pragma unroll
            for (int j = 0; j < 4; j++) sacc[i][j] = 0.f;

#pragma unroll
        for (int kf = 0; kf < 6; kf++) {
            uint32_t qoff = (uint32_t)(w * 16 + (lane & 15)) * SQp + kf * 32 + (lane >> 4) * 16;
            uint32_t ah[4], al[4];
            ldsm_x4(ah, sb + OFF_QH + qoff);
            ldsm_x4(al, sb + OFF_QL + qoff);
#pragma unroll
            for (int p = 0; p < 8; p++) {
                uint32_t koff = (uint32_t)(p * 16 + (lane & 15)) * SQp + kf * 32 + (lane >> 4) * 16;
                uint32_t kh4[4], kl4[4];
                ldsm_x4(kh4, sb + OFF_KH + koff);
                ldsm_x4(kl4, sb + OFF_KL + koff);
                uint32_t b0h[2] = {kh4[0], kh4[2]}, b1h[2] = {kh4[1], kh4[3]};
                uint32_t b0l[2] = {kl4[0], kl4[2]}, b1l[2] = {kl4[1], kl4[3]};
                mma_16816(sacc[2 * p],     ah, b0h);
                mma_16816(sacc[2 * p],     ah, b0l);
                mma_16816(sacc[2 * p],     al, b0h);
                mma_16816(sacc[2 * p + 1], ah, b1h);
                mma_16816(sacc[2 * p + 1], ah, b1l);
                mma_16816(sacc[2 * p + 1], al, b1h);
            }
        }

        // ---- causal mask (diagonal tile only) ----
        if (kt == qt) {
            const int lr0 = w * 16 + (lane >> 2), lr1 = lr0 + 8;
#pragma unroll
            for (int nf = 0; nf < 16; nf++) {
                int lc = nf * 8 + (lane & 3) * 2;
                if (lc     > lr0) sacc[nf][0] = -1e30f;
                if (lc + 1 > lr0) sacc[nf][1] = -1e30f;
                if (lc     > lr1) sacc[nf][2] = -1e30f;
                if (lc + 1 > lr1) sacc[nf][3] = -1e30f;
            }
        }

        // ---- online softmax (rows r0 = lane>>2, r1 = r0+8; quad = lane&3) ----
        float tm0 = -1e30f, tm1 = -1e30f;
#pragma unroll
        for (int nf = 0; nf < 16; nf++) {
            tm0 = fmaxf(tm0, fmaxf(sacc[nf][0], sacc[nf][1]));
            tm1 = fmaxf(tm1, fmaxf(sacc[nf][2], sacc[nf][3]));
        }
        tm0 = fmaxf(tm0, __shfl_xor_sync(0xffffffffu, tm0, 1));
        tm0 = fmaxf(tm0, __shfl_xor_sync(0xffffffffu, tm0, 2));
        tm1 = fmaxf(tm1, __shfl_xor_sync(0xffffffffu, tm1, 1));
        tm1 = fmaxf(tm1, __shfl_xor_sync(0xffffffffu, tm1, 2));
        float nm0 = fmaxf(m0, tm0), nm1 = fmaxf(m1, tm1);
        float c0 = __expf(m0 - nm0), c1 = __expf(m1 - nm1);
        m0 = nm0; m1 = nm1;
        float ts0 = 0.f, ts1 = 0.f;
#pragma unroll
        for (int nf = 0; nf < 16; nf++) {
            sacc[nf][0] = __expf(sacc[nf][0] - nm0);
            sacc[nf][1] = __expf(sacc[nf][1] - nm0);
            sacc[nf][2] = __expf(sacc[nf][2] - nm1);
            sacc[nf][3] = __expf(sacc[nf][3] - nm1);
            ts0 += sacc[nf][0] + sacc[nf][1];
            ts1 += sacc[nf][2] + sacc[nf][3];
        }
        ts0 += __shfl_xor_sync(0xffffffffu, ts0, 1);
        ts0 += __shfl_xor_sync(0xffffffffu, ts0, 2);
        ts1 += __shfl_xor_sync(0xffffffffu, ts1, 1);
        ts1 += __shfl_xor_sync(0xffffffffu, ts1, 2);
        l0 = l0 * c0 + ts0;
        l1 = l1 * c1 + ts1;
#pragma unroll
        for (int nf = 0; nf < 12; nf++) {
            oacc[nf][0] *= c0; oacc[nf][1] *= c0;
            oacc[nf][2] *= c1; oacc[nf][3] *= c1;
        }

        // ---- O += P V (P from S accumulators, 3-term split) ----
#pragma unroll
        for (int t = 0; t < 8; t++) {
            uint32_t pah[4], pal[4];
            split2w(sacc[2 * t][0],     sacc[2 * t][1],     pah[0], pal[0]);
            split2w(sacc[2 * t][2],     sacc[2 * t][3],     pah[1], pal[1]);
            split2w(sacc[2 * t + 1][0], sacc[2 * t + 1][1], pah[2], pal[2]);
            split2w(sacc[2 * t + 1][2], sacc[2 * t + 1][3], pah[3], pal[3]);
#pragma unroll
            for (int dp = 0; dp < 6; dp++) {
                uint32_t voff = (uint32_t)(dp * 16 + (lane & 15)) * SVp + t * 32 + (lane >> 4) * 16;
                uint32_t vh4[4], vl4[4];
                ldsm_x4(vh4, sb + OFF_VH + voff);
                ldsm_x4(vl4, sb + OFF_VL + voff);
                uint32_t b0h[2] = {vh4[0], vh4[2]}, b1h[2] = {vh4[1], vh4[3]};
                uint32_t b0l[2] = {vl4[0], vl4[2]}, b1l[2] = {vl4[1], vl4[3]};
                mma_16816(oacc[2 * dp],     pah, b0h);
                mma_16816(oacc[2 * dp],     pah, b0l);
                mma_16816(oacc[2 * dp],     pal, b0h);
                mma_16816(oacc[2 * dp + 1], pah, b1h);
                mma_16816(oacc[2 * dp + 1], pah, b1l);
                mma_16816(oacc[2 * dp + 1], pal, b1h);
            }
        }
    }

    // ---- epilogue: normalize, write y split bf16 [B*T, C] ----
    const float i0 = 1.f / l0, i1 = 1.f / l1;
    const size_t row0 = (size_t)b * Tn + qt * 128 + w * 16 + (lane >> 2);
#pragma unroll
    for (int nf = 0; nf < 12; nf++) {
        int col = h * Dn + nf * 8 + (lane & 3) * 2;
        uint32_t hh, ll;
        split2w(oacc[nf][0] * i0, oacc[nf][1] * i0, hh, ll);
        *(uint32_t*)(g_yh + row0 * Cn + col) = hh;
        *(uint32_t*)(g_yl + row0 * Cn + col) = ll;
        split2w(oacc[nf][2] * i1, oacc[nf][3] * i1, hh, ll);
        *(uint32_t*)(g_yh + (row0 + 8) * Cn + col) = hh;
        *(uint32_t*)(g_yl + (row0 + 8) * Cn + col) = ll;
    }
}

// ---------------------------------------------------------------------------
// Launch pipeline
// ---------------------------------------------------------------------------
extern "C" void kernel_launch(void* const* d_in, const int* in_sizes, int n_in,
                              void* d_out, int out_size)
{
    const float* x      = (const float*)d_in[0];
    const float* W_attn = (const float*)d_in[1];
    const float* b_attn = (const float*)d_in[2];
    const float* W_proj = (const float*)d_in[3];
    const float* b_proj = (const float*)d_in[4];
    float* out = (float*)d_out;

    float* qkv;
    __nv_bfloat16 *xh, *xl, *yh, *yl, *wath, *watl, *wpth, *wptl;
    cudaGetSymbolAddress((void**)&qkv,  g_qkv);
    cudaGetSymbolAddress((void**)&xh,   g_xh);
    cudaGetSymbolAddress((void**)&xl,   g_xl);
    cudaGetSymbolAddress((void**)&yh,   g_yh);
    cudaGetSymbolAddress((void**)&yl,   g_yl);
    cudaGetSymbolAddress((void**)&wath, g_WaTh);
    cudaGetSymbolAddress((void**)&watl, g_WaTl);
    cudaGetSymbolAddress((void**)&wpth, g_WpTh);
    cudaGetSymbolAddress((void**)&wptl, g_WpTl);

    cudaFuncSetAttribute(tensor_gemm,
                         cudaFuncAttributeMaxDynamicSharedMemorySize, GEMM_SMEM_DYN);
    cudaFuncSetAttribute(attention_mma,
                         cudaFuncAttributeMaxDynamicSharedMemorySize, ATT_SMEM);

    const int n4x = (Mn * Cn) / 4;
    split_fp32<<<(n4x + 255) / 256, 256>>>(x, xh, xl, n4x);
    transpose_split<<<dim3(N3 / 32, Kd / 32), 256>>>(W_attn, wath, watl, N3);
    transpose_split<<<dim3(Cn / 32, Kd / 32), 256>>>(W_proj, wpth, wptl, Cn);

    // 1) qkv = x @ W_attn + b_attn   [8192, 2304]
    tensor_gemm<<<dim3(N3 / 128, Mn / 128), 256, GEMM_SMEM_DYN>>>(
        xh, xl, wath, watl, b_attn, qkv, N3);

    // 2) attention operand prep + flash attention (tensor cores)
    attn_prep<<<dim3(Mn / 128, Hn), 256>>>();
    attention_mma<<<dim3(Tn / 128, Bn * Hn), 256, ATT_SMEM>>>();

    // 3) out = y @ W_proj + b_proj   [8192, 768]
    tensor_gemm<<<dim3(Cn / 128, Mn / 128), 256, GEMM_SMEM_DYN>>>(
        yh, yl, wpth, wptl, b_proj, out, Cn);
}

// round 9
// speedup vs baseline: 2.2498x; 1.1008x over previous
#include <cuda_runtime.h>
#include <cuda_bf16.h>
#include <cstdint>

// Problem shape (fixed by the reference)
#define Bn 8
#define Tn 1024
#define Cn 768
#define Hn 8
#define Dn 96
#define Mn (Bn*Tn)      // 8192 rows
#define N3 (3*Cn)       // 2304
#define Kd 768

// ---------------------------------------------------------------------------
// Scratch (allocation-free rule: __device__ globals)
// ---------------------------------------------------------------------------
__device__ float g_qkv[(size_t)Mn * N3];   // [B*T, 3C]
__device__ __nv_bfloat16 g_xh[(size_t)Mn * Cn], g_xl[(size_t)Mn * Cn];
__device__ __nv_bfloat16 g_yh[(size_t)Mn * Cn], g_yl[(size_t)Mn * Cn];
__device__ __nv_bfloat16 g_WaTh[(size_t)N3 * Cn], g_WaTl[(size_t)N3 * Cn];
__device__ __nv_bfloat16 g_WpTh[(size_t)Cn * Cn], g_WpTl[(size_t)Cn * Cn];
// Attention operands: [bh][1024][96] for Q,K; [bh][96][1024] for V^T
#define AQE ((size_t)Bn * Hn * Tn * Dn)
__device__ __nv_bfloat16 g_Qh[AQE], g_Ql[AQE];
__device__ __nv_bfloat16 g_Kh[AQE], g_Kl[AQE];
__device__ __nv_bfloat16 g_VTh[AQE], g_VTl[AQE];

// ---------------------------------------------------------------------------
// Portable tensor-core primitives (sm_80+, legal at .target sm_103)
// ---------------------------------------------------------------------------
__device__ __forceinline__ uint32_t smem_u32(const void* p) {
    uint32_t a;
    asm("{ .reg .u64 t; cvta.to.shared.u64 t, %1; cvt.u32.u64 %0, t; }" : "=r"(a) : "l"(p));
    return a;
}
__device__ __forceinline__ void ldsm_x4(uint32_t* r, uint32_t addr) {
    asm volatile("ldmatrix.sync.aligned.m8n8.x4.shared.b16 {%0,%1,%2,%3}, [%4];"
                 : "=r"(r[0]), "=r"(r[1]), "=r"(r[2]), "=r"(r[3]) : "r"(addr));
}
__device__ __forceinline__ void mma_16816(float* c, const uint32_t* a, const uint32_t* b) {
    asm volatile("mma.sync.aligned.m16n8k16.row.col.f32.bf16.bf16.f32 "
                 "{%0,%1,%2,%3}, {%4,%5,%6,%7}, {%8,%9}, {%0,%1,%2,%3};"
                 : "+f"(c[0]), "+f"(c[1]), "+f"(c[2]), "+f"(c[3])
                 : "r"(a[0]), "r"(a[1]), "r"(a[2]), "r"(a[3]), "r"(b[0]), "r"(b[1]));
}
__device__ __forceinline__ void cp16(uint32_t saddr, const void* g) {
    asm volatile("cp.async.cg.shared.global [%0], [%1], 16;" :: "r"(saddr), "l"(g));
}
#define CP_COMMIT() asm volatile("cp.async.commit_group;" ::: "memory")
#define CP_WAIT0()  asm volatile("cp.async.wait_group 0;" ::: "memory")
#define CP_WAIT1()  asm volatile("cp.async.wait_group 1;" ::: "memory")

// Split a float pair into bf16x2 hi + lo words
__device__ __forceinline__ void split2w(float a, float b, uint32_t& h, uint32_t& l) {
    __nv_bfloat16 ha = __float2bfloat16(a), hb = __float2bfloat16(b);
    __nv_bfloat162 H; H.x = ha; H.y = hb;
    __nv_bfloat162 L;
    L.x = __float2bfloat16(a - __bfloat162float(ha));
    L.y = __float2bfloat16(b - __bfloat162float(hb));
    h = *(uint32_t*)&H; l = *(uint32_t*)&L;
}

// ---------------------------------------------------------------------------
// Conversion kernels
// ---------------------------------------------------------------------------
__global__ __launch_bounds__(256)
void split_fp32(const float* __restrict__ src, __nv_bfloat16* __restrict__ hi,
                __nv_bfloat16* __restrict__ lo, int n4)
{
    int i = blockIdx.x * blockDim.x + threadIdx.x;
    if (i >= n4) return;
    float4 v = ((const float4*)src)[i];
    uint32_t h0, l0, h1, l1;
    split2w(v.x, v.y, h0, l0);
    split2w(v.z, v.w, h1, l1);
    ((uint32_t*)hi)[i * 2] = h0; ((uint32_t*)hi)[i * 2 + 1] = h1;
    ((uint32_t*)lo)[i * 2] = l0; ((uint32_t*)lo)[i * 2 + 1] = l1;
}

// W[K=768, Ndim] row-major -> transposed split bf16 [Ndim, 768]
__global__ __launch_bounds__(256)
void transpose_split(const float* __restrict__ W, __nv_bfloat16* __restrict__ Th,
                     __nv_bfloat16* __restrict__ Tl, int Ndim)
{
    __shared__ float t[32][33];
    int tx = threadIdx.x & 31, ty = threadIdx.x >> 5;
    int n0 = blockIdx.x * 32, k0 = blockIdx.y * 32;
#pragma unroll
    for (int i = 0; i < 32; i += 8)
        t[ty + i][tx] = W[(size_t)(k0 + ty + i) * Ndim + n0 + tx];
    __syncthreads();
#pragma unroll
    for (int i = 0; i < 32; i += 8) {
        float v = t[tx][ty + i];
        __nv_bfloat16 h = __float2bfloat16(v);
        size_t o = (size_t)(n0 + ty + i) * Kd + k0 + tx;
        Th[o] = h;
        Tl[o] = __float2bfloat16(v - __bfloat162float(h));
    }
}

// qkv fp32 -> attention operands: Qh/Ql (pre-scaled), Kh/Kl, VTh/VTl (transposed)
__global__ __launch_bounds__(256)
void attn_prep()
{
    __shared__ float vs[128][101];
    const int tt = blockIdx.x;     // token tile 0..63 (global over 8192)
    const int h  = blockIdx.y;     // head
    const int tid = threadIdx.x;
    const int b = tt >> 3;
    const int bh = b * Hn + h;
    const int tloc = (tt & 7) * 128;
    const float* base = g_qkv + (size_t)tt * 128 * N3 + h * Dn;
    const float scale = rsqrtf((float)Dn);

    uint32_t* Qh2 = (uint32_t*)(g_Qh + ((size_t)bh * Tn + tloc) * Dn);
    uint32_t* Ql2 = (uint32_t*)(g_Ql + ((size_t)bh * Tn + tloc) * Dn);
    uint32_t* Kh2 = (uint32_t*)(g_Kh + ((size_t)bh * Tn + tloc) * Dn);
    uint32_t* Kl2 = (uint32_t*)(g_Kl + ((size_t)bh * Tn + tloc) * Dn);

    for (int i = tid; i < 128 * 24; i += 256) {
        int row = i / 24, j = i - row * 24;
        const float* p = base + (size_t)row * N3 + j * 4;
        float4 q = *(const float4*)(p);
        float4 k = *(const float4*)(p + Cn);
        float4 v = *(const float4*)(p + 2 * Cn);
        uint32_t h0, l0, h1, l1;
        split2w(q.x * scale, q.y * scale, h0, l0);
        split2w(q.z * scale, q.w * scale, h1, l1);
        int o = row * 48 + j * 2;
        Qh2[o] = h0; Qh2[o + 1] = h1; Ql2[o] = l0; Ql2[o + 1] = l1;
        split2w(k.x, k.y, h0, l0);
        split2w(k.z, k.w, h1, l1);
        Kh2[o] = h0; Kh2[o + 1] = h1; Kl2[o] = l0; Kl2[o + 1] = l1;
        vs[row][j * 4 + 0] = v.x; vs[row][j * 4 + 1] = v.y;
        vs[row][j * 4 + 2] = v.z; vs[row][j * 4 + 3] = v.w;
    }
    __syncthreads();
    for (int i = tid; i < 96 * 64; i += 256) {
        int d = i >> 6, tp = i & 63;
        uint32_t hh, ll;
        split2w(vs[2 * tp][d], vs[2 * tp + 1][d], hh, ll);
        size_t o = (((size_t)bh * Dn + d) * Tn + tloc) / 2 + tp;
        ((uint32_t*)g_VTh)[o] = hh;
        ((uint32_t*)g_VTl)[o] = ll;
    }
}

// ---------------------------------------------------------------------------
// Tensor-core GEMM via mma.sync (bf16 3-term split), 3-stage cp.async
// pipeline, BK=64, one __syncthreads per K-tile.
//   Cout[M, Ndim] = (Ah+Al)[M,768] @ (BTh+BTl)[Ndim,768]^T + bias
// CTA 128x128, 8 warps of 64x32.  Smem rows 144B (9x16B): chunk index
// 9r mod 8 is a permutation -> conflict-free ldmatrix.
// ---------------------------------------------------------------------------
#define ROWB 144
#define TILEB (128 * ROWB)          // 18432 B per 128x64-bf16 tile
#define STAGEB (4 * TILEB)          // Ah | Al | Bh | Bl = 73728 B
#define GEMM_SMEM_DYN (3 * STAGEB)  // 221184 B

extern __shared__ float sm_dyn[];

__device__ __forceinline__ void gemm_issue_stage(
    const __nv_bfloat16* const* tp, uint32_t sdst, int kt, int tid)
{
#pragma unroll
    for (int i = 0; i < 16; i++) {
        int id = i * 256 + tid;
        int tile = id >> 10;
        int r = (id >> 3) & 127;
        int c = id & 7;
        const __nv_bfloat16* g = tp[tile] + (size_t)r * Kd + kt * 64 + c * 8;
        cp16(sdst + tile * TILEB + r * ROWB + c * 16, g);
    }
    CP_COMMIT();
}

__global__ __launch_bounds__(256, 1)
void tensor_gemm(const __nv_bfloat16* __restrict__ Ah, const __nv_bfloat16* __restrict__ Al,
                 const __nv_bfloat16* __restrict__ BTh, const __nv_bfloat16* __restrict__ BTl,
                 const float* __restrict__ bias, float* __restrict__ Cout, int Ndim)
{
    const int tid = threadIdx.x;
    const int wid = tid >> 5, lane = tid & 31;
    const int m0 = blockIdx.y * 128;
    const int n0 = blockIdx.x * 128;
    const int wm = (wid >> 2) * 64;
    const int wn = (wid & 3) * 32;

    const uint32_t sbase = smem_u32(sm_dyn);

    const __nv_bfloat16* tp[4] = {
        Ah  + (size_t)m0 * Kd, Al  + (size_t)m0 * Kd,
        BTh + (size_t)n0 * Kd, BTl + (size_t)n0 * Kd
    };

    float acc[4][4][4];
#pragma unroll
    for (int mf = 0; mf < 4; mf++)
#pragma unroll
        for (int nf = 0; nf < 4; nf++)
#pragma unroll
            for (int j = 0; j < 4; j++) acc[mf][nf][j] = 0.f;

    // ldmatrix lane-address components
    const int arow = wm + (lane & 15);
    const int akb  = (lane >> 4) << 3;                              // A: k half
    const int brow = wn + (lane & 7) + ((lane >> 4) << 3);          // B: row within 16-pair
    const int bkb  = ((lane >> 3) & 1) << 3;                        // B: k half

    gemm_issue_stage(tp, sbase, 0, tid);
    gemm_issue_stage(tp, sbase + STAGEB, 1, tid);

    for (int kt = 0; kt < 12; kt++) {
        if (kt < 11) CP_WAIT1(); else CP_WAIT0();
        __syncthreads();

        // prefetch stage kt+2 (overlaps with compute below)
        if (kt + 2 < 12)
            gemm_issue_stage(tp, sbase + ((kt + 2) % 3) * STAGEB, kt + 2, tid);

        const uint32_t Ahb = sbase + (kt % 3) * STAGEB;
        const uint32_t Alb = Ahb + TILEB;
        const uint32_t Bhb = Ahb + 2 * TILEB;
        const uint32_t Blb = Ahb + 3 * TILEB;

#pragma unroll
        for (int kf = 0; kf < 4; kf++) {
            const int kb = kf * 16;
            uint32_t ah[4][4], al[4][4], bh[4][2], bl[4][2];
#pragma unroll
            for (int mf = 0; mf < 4; mf++) {
                uint32_t off = (uint32_t)(arow + mf * 16) * ROWB + (kb + akb) * 2;
                ldsm_x4(ah[mf], Ahb + off);
                ldsm_x4(al[mf], Alb + off);
            }
#pragma unroll
            for (int np = 0; np < 2; np++) {
                uint32_t off = (uint32_t)(brow + np * 16) * ROWB + (kb + bkb) * 2;
                uint32_t t4[4];
                ldsm_x4(t4, Bhb + off);
                bh[2 * np][0] = t4[0]; bh[2 * np][1] = t4[1];
                bh[2 * np + 1][0] = t4[2]; bh[2 * np + 1][1] = t4[3];
                ldsm_x4(t4, Blb + off);
                bl[2 * np][0] = t4[0]; bl[2 * np][1] = t4[1];
                bl[2 * np + 1][0] = t4[2]; bl[2 * np + 1][1] = t4[3];
            }
#pragma unroll
            for (int mf = 0; mf < 4; mf++)
#pragma unroll
                for (int nf = 0; nf < 4; nf++) {
                    mma_16816(acc[mf][nf], ah[mf], bh[nf]);
                    mma_16816(acc[mf][nf], ah[mf], bl[nf]);
                    mma_16816(acc[mf][nf], al[mf], bh[nf]);
                }
        }
    }

    // Epilogue
    const int mrow = m0 + wm + (lane >> 2);
    const int ncol = n0 + wn + (lane & 3) * 2;
#pragma unroll
    for (int mf = 0; mf < 4; mf++)
#pragma unroll
        for (int nf = 0; nf < 4; nf++) {
            int r = mrow + mf * 16, c = ncol + nf * 8;
            float b0 = bias[c], b1 = bias[c + 1];
            *(float2*)(Cout + (size_t)r * Ndim + c) =
                make_float2(acc[mf][nf][0] + b0, acc[mf][nf][1] + b1);
            *(float2*)(Cout + (size_t)(r + 8) * Ndim + c) =
                make_float2(acc[mf][nf][2] + b0, acc[mf][nf][3] + b1);
        }
}

// ---------------------------------------------------------------------------
// Tensor-core flash attention (unchanged from R8 passing kernel).
// grid = (8 q-tiles, 64 bh), 256 threads; warp w owns q-rows [w*16, w*16+16).
// ---------------------------------------------------------------------------
#define SQp 208
#define SVp 272
#define OFF_QH 0
#define OFF_QL (128 * SQp)
#define OFF_KH (2 * 128 * SQp)
#define OFF_KL (3 * 128 * SQp)
#define OFF_VH (4 * 128 * SQp)
#define OFF_VL (4 * 128 * SQp + 96 * SVp)
#define ATT_SMEM (4 * 128 * SQp + 2 * 96 * SVp)   // 158720 B

__device__ __forceinline__ void ldsm_x2(uint32_t* r, uint32_t addr) {
    asm volatile("ldmatrix.sync.aligned.m8n8.x2.shared.b16 {%0,%1}, [%2];"
                 : "=r"(r[0]), "=r"(r[1]) : "r"(addr));
}

__global__ __launch_bounds__(256, 1)
void attention_mma()
{
    const int tid = threadIdx.x, lane = tid & 31, w = tid >> 5;
    const int qt = blockIdx.x, bh = blockIdx.y;
    const int b = bh >> 3, h = bh & 7;
    const uint32_t sb = smem_u32(sm_dyn);

    const __nv_bfloat16* gQh = g_Qh + ((size_t)bh * Tn + qt * 128) * Dn;
    const __nv_bfloat16* gQl = g_Ql + ((size_t)bh * Tn + qt * 128) * Dn;
    const __nv_bfloat16* gKh = g_Kh + (size_t)bh * Tn * Dn;
    const __nv_bfloat16* gKl = g_Kl + (size_t)bh * Tn * Dn;
    const __nv_bfloat16* gVh = g_VTh + (size_t)bh * Dn * Tn;
    const __nv_bfloat16* gVl = g_VTl + (size_t)bh * Dn * Tn;

    for (int i = tid; i < 128 * 12; i += 256) {
        int r = i / 12, c = i - r * 12;
        cp16(sb + OFF_QH + r * SQp + c * 16, gQh + r * Dn + c * 8);
        cp16(sb + OFF_QL + r * SQp + c * 16, gQl + r * Dn + c * 8);
    }
    CP_COMMIT();

    float oacc[12][4];
#pragma unroll
    for (int i = 0; i < 12; i++)
#pragma unroll
        for (int j = 0; j < 4; j++) oacc[i][j] = 0.f;
    float m0 = -1e30f, m1 = -1e30f, l0 = 0.f, l1 = 0.f;

    for (int kt = 0; kt <= qt; kt++) {
        if (kt) __syncthreads();
        const __nv_bfloat16* kh = gKh + (size_t)kt * 128 * Dn;
        const __nv_bfloat16* kl = gKl + (size_t)kt * 128 * Dn;
        for (int i = tid; i < 128 * 12; i += 256) {
            int r = i / 12, c = i - r * 12;
            cp16(sb + OFF_KH + r * SQp + c * 16, kh + r * Dn + c * 8);
            cp16(sb + OFF_KL + r * SQp + c * 16, kl + r * Dn + c * 8);
        }
        for (int i = tid; i < 96 * 16; i += 256) {
            int d = i >> 4, c = i & 15;
            cp16(sb + OFF_VH + d * SVp + c * 16, gVh + (size_t)d * Tn + kt * 128 + c * 8);
            cp16(sb + OFF_VL + d * SVp + c * 16, gVl + (size_t)d * Tn + kt * 128 + c * 8);
        }
        CP_COMMIT();
        CP_WAIT0();
        __syncthreads();

        // ---- S = Q K^T (3-term split) ----
        float sacc[16][4];
#pragma unroll
        for (int i = 0; i < 16; i++)
#pragma unroll
            for (int j = 0; j < 4; j++) sacc[i][j] = 0.f;

#pragma unroll
        for (int kf = 0; kf < 6; kf++) {
            uint32_t qoff = (uint32_t)(w * 16 + (lane & 15)) * SQp + kf * 32 + (lane >> 4) * 16;
            uint32_t ah[4], al[4];
            ldsm_x4(ah, sb + OFF_QH + qoff);
            ldsm_x4(al, sb + OFF_QL + qoff);
#pragma unroll
            for (int p = 0; p < 8; p++) {
                uint32_t koff = (uint32_t)(p * 16 + (lane & 15)) * SQp + kf * 32 + (lane >> 4) * 16;
                uint32_t kh4[4], kl4[4];
                ldsm_x4(kh4, sb + OFF_KH + koff);
                ldsm_x4(kl4, sb + OFF_KL + koff);
                uint32_t b0h[2] = {kh4[0], kh4[2]}, b1h[2] = {kh4[1], kh4[3]};
                uint32_t b0l[2] = {kl4[0], kl4[2]}, b1l[2] = {kl4[1], kl4[3]};
                mma_16816(sacc[2 * p],     ah, b0h);
                mma_16816(sacc[2 * p],     ah, b0l);
                mma_16816(sacc[2 * p],     al, b0h);
                mma_16816(sacc[2 * p + 1], ah, b1h);
                mma_16816(sacc[2 * p + 1], ah, b1l);
                mma_16816(sacc[2 * p + 1], al, b1h);
            }
        }

        if (kt == qt) {
            const int lr0 = w * 16 + (lane >> 2), lr1 = lr0 + 8;
#pragma unroll
            for (int nf = 0; nf < 16; nf++) {
                int lc = nf * 8 + (lane & 3) * 2;
                if (lc     > lr0) sacc[nf][0] = -1e30f;
                if (lc + 1 > lr0) sacc[nf][1] = -1e30f;
                if (lc     > lr1) sacc[nf][2] = -1e30f;
                if (lc + 1 > lr1) sacc[nf][3] = -1e30f;
            }
        }

        // ---- online softmax ----
        float tm0 = -1e30f, tm1 = -1e30f;
#pragma unroll
        for (int nf = 0; nf < 16; nf++) {
            tm0 = fmaxf(tm0, fmaxf(sacc[nf][0], sacc[nf][1]));
            tm1 = fmaxf(tm1, fmaxf(sacc[nf][2], sacc[nf][3]));
        }
        tm0 = fmaxf(tm0, __shfl_xor_sync(0xffffffffu, tm0, 1));
        tm0 = fmaxf(tm0, __shfl_xor_sync(0xffffffffu, tm0, 2));
        tm1 = fmaxf(tm1, __shfl_xor_sync(0xffffffffu, tm1, 1));
        tm1 = fmaxf(tm1, __shfl_xor_sync(0xffffffffu, tm1, 2));
        float nm0 = fmaxf(m0, tm0), nm1 = fmaxf(m1, tm1);
        float c0 = __expf(m0 - nm0), c1 = __expf(m1 - nm1);
        m0 = nm0; m1 = nm1;
        float ts0 = 0.f, ts1 = 0.f;
#pragma unroll
        for (int nf = 0; nf < 16; nf++) {
            sacc[nf][0] = __expf(sacc[nf][0] - nm0);
            sacc[nf][1] = __expf(sacc[nf][1] - nm0);
            sacc[nf][2] = __expf(sacc[nf][2] - nm1);
            sacc[nf][3] = __expf(sacc[nf][3] - nm1);
            ts0 += sacc[nf][0] + sacc[nf][1];
            ts1 += sacc[nf][2] + sacc[nf][3];
        }
        ts0 += __shfl_xor_sync(0xffffffffu, ts0, 1);
        ts0 += __shfl_xor_sync(0xffffffffu, ts0, 2);
        ts1 += __shfl_xor_sync(0xffffffffu, ts1, 1);
        ts1 += __shfl_xor_sync(0xffffffffu, ts1, 2);
        l0 = l0 * c0 + ts0;
        l1 = l1 * c1 + ts1;
#pragma unroll
        for (int nf = 0; nf < 12; nf++) {
            oacc[nf][0] *= c0; oacc[nf][1] *= c0;
            oacc[nf][2] *= c1; oacc[nf][3] *= c1;
        }

        // ---- O += P V (P from S accumulators, 3-term split) ----
#pragma unroll
        for (int t = 0; t < 8; t++) {
            uint32_t pah[4], pal[4];
            split2w(sacc[2 * t][0],     sacc[2 * t][1],     pah[0], pal[0]);
            split2w(sacc[2 * t][2],     sacc[2 * t][3],     pah[1], pal[1]);
            split2w(sacc[2 * t + 1][0], sacc[2 * t + 1][1], pah[2], pal[2]);
            split2w(sacc[2 * t + 1][2], sacc[2 * t + 1][3], pah[3], pal[3]);
#pragma unroll
            for (int dp = 0; dp < 6; dp++) {
                uint32_t voff = (uint32_t)(dp * 16 + (lane & 15)) * SVp + t * 32 + (lane >> 4) * 16;
                uint32_t vh4[4], vl4[4];
                ldsm_x4(vh4, sb + OFF_VH + voff);
                ldsm_x4(vl4, sb + OFF_VL + voff);
                uint32_t b0h[2] = {vh4[0], vh4[2]}, b1h[2] = {vh4[1], vh4[3]};
                uint32_t b0l[2] = {vl4[0], vl4[2]}, b1l[2] = {vl4[1], vl4[3]};
                mma_16816(oacc[2 * dp],     pah, b0h);
                mma_16816(oacc[2 * dp],     pah, b0l);
                mma_16816(oacc[2 * dp],     pal, b0h);
                mma_16816(oacc[2 * dp + 1], pah, b1h);
                mma_16816(oacc[2 * dp + 1], pah, b1l);
                mma_16816(oacc[2 * dp + 1], pal, b1h);
            }
        }
    }

    // ---- epilogue: normalize, write y split bf16 [B*T, C] ----
    const float i0 = 1.f / l0, i1 = 1.f / l1;
    const size_t row0 = (size_t)b * Tn + qt * 128 + w * 16 + (lane >> 2);
#pragma unroll
    for (int nf = 0; nf < 12; nf++) {
        int col = h * Dn + nf * 8 + (lane & 3) * 2;
        uint32_t hh, ll;
        split2w(oacc[nf][0] * i0, oacc[nf][1] * i0, hh, ll);
        *(uint32_t*)(g_yh + row0 * Cn + col) = hh;
        *(uint32_t*)(g_yl + row0 * Cn + col) = ll;
        split2w(oacc[nf][2] * i1, oacc[nf][3] * i1, hh, ll);
        *(uint32_t*)(g_yh + (row0 + 8) * Cn + col) = hh;
        *(uint32_t*)(g_yl + (row0 + 8) * Cn + col) = ll;
    }
}

// ---------------------------------------------------------------------------
// Launch pipeline
// ---------------------------------------------------------------------------
extern "C" void kernel_launch(void* const* d_in, const int* in_sizes, int n_in,
                              void* d_out, int out_size)
{
    const float* x      = (const float*)d_in[0];
    const float* W_attn = (const float*)d_in[1];
    const float* b_attn = (const float*)d_in[2];
    const float* W_proj = (const float*)d_in[3];
    const float* b_proj = (const float*)d_in[4];
    float* out = (float*)d_out;

    float* qkv;
    __nv_bfloat16 *xh, *xl, *yh, *yl, *wath, *watl, *wpth, *wptl;
    cudaGetSymbolAddress((void**)&qkv,  g_qkv);
    cudaGetSymbolAddress((void**)&xh,   g_xh);
    cudaGetSymbolAddress((void**)&xl,   g_xl);
    cudaGetSymbolAddress((void**)&yh,   g_yh);
    cudaGetSymbolAddress((void**)&yl,   g_yl);
    cudaGetSymbolAddress((void**)&wath, g_WaTh);
    cudaGetSymbolAddress((void**)&watl, g_WaTl);
    cudaGetSymbolAddress((void**)&wpth, g_WpTh);
    cudaGetSymbolAddress((void**)&wptl, g_WpTl);

    cudaFuncSetAttribute(tensor_gemm,
                         cudaFuncAttributeMaxDynamicSharedMemorySize, GEMM_SMEM_DYN);
    cudaFuncSetAttribute(attention_mma,
                         cudaFuncAttributeMaxDynamicSharedMemorySize, ATT_SMEM);

    const int n4x = (Mn * Cn) / 4;
    split_fp32<<<(n4x + 255) / 256, 256>>>(x, xh, xl, n4x);
    transpose_split<<<dim3(N3 / 32, Kd / 32), 256>>>(W_attn, wath, watl, N3);
    transpose_split<<<dim3(Cn / 32, Kd / 32), 256>>>(W_proj, wpth, wptl, Cn);

    // 1) qkv = x @ W_attn + b_attn   [8192, 2304]
    tensor_gemm<<<dim3(N3 / 128, Mn / 128), 256, GEMM_SMEM_DYN>>>(
        xh, xl, wath, watl, b_attn, qkv, N3);

    // 2) attention operand prep + flash attention (tensor cores)
    attn_prep<<<dim3(Mn / 128, Hn), 256>>>();
    attention_mma<<<dim3(Tn / 128, Bn * Hn), 256, ATT_SMEM>>>();

    // 3) out = y @ W_proj + b_proj   [8192, 768]
    tensor_gemm<<<dim3(Cn / 128, Mn / 128), 256, GEMM_SMEM_DYN>>>(
        yh, yl, wpth, wptl, b_proj, out, Cn);
}

// round 10
// speedup vs baseline: 2.2626x; 1.0057x over previous
#include <cuda_runtime.h>
#include <cuda_bf16.h>
#include <cstdint>

// Problem shape (fixed by the reference)
#define Bn 8
#define Tn 1024
#define Cn 768
#define Hn 8
#define Dn 96
#define Mn (Bn*Tn)      // 8192 rows
#define N3 (3*Cn)       // 2304
#define Kd 768

// ---------------------------------------------------------------------------
// Scratch (allocation-free rule: __device__ globals)
// ---------------------------------------------------------------------------
__device__ float g_qkv[(size_t)Mn * N3];   // [B*T, 3C]
__device__ __nv_bfloat16 g_xh[(size_t)Mn * Cn], g_xl[(size_t)Mn * Cn];
__device__ __nv_bfloat16 g_yh[(size_t)Mn * Cn], g_yl[(size_t)Mn * Cn];
__device__ __nv_bfloat16 g_WaTh[(size_t)N3 * Cn], g_WaTl[(size_t)N3 * Cn];
__device__ __nv_bfloat16 g_WpTh[(size_t)Cn * Cn], g_WpTl[(size_t)Cn * Cn];
// Attention operands: [bh][1024][96] for Q,K; [bh][96][1024] for V^T
#define AQE ((size_t)Bn * Hn * Tn * Dn)
__device__ __nv_bfloat16 g_Qh[AQE], g_Ql[AQE];
__device__ __nv_bfloat16 g_Kh[AQE], g_Kl[AQE];
__device__ __nv_bfloat16 g_VTh[AQE], g_VTl[AQE];

// ---------------------------------------------------------------------------
// Portable tensor-core primitives (sm_80+, legal at .target sm_103)
// ---------------------------------------------------------------------------
__device__ __forceinline__ uint32_t smem_u32(const void* p) {
    uint32_t a;
    asm("{ .reg .u64 t; cvta.to.shared.u64 t, %1; cvt.u32.u64 %0, t; }" : "=r"(a) : "l"(p));
    return a;
}
__device__ __forceinline__ void ldsm_x4(uint32_t* r, uint32_t addr) {
    asm volatile("ldmatrix.sync.aligned.m8n8.x4.shared.b16 {%0,%1,%2,%3}, [%4];"
                 : "=r"(r[0]), "=r"(r[1]), "=r"(r[2]), "=r"(r[3]) : "r"(addr));
}
__device__ __forceinline__ void mma_16816(float* c, const uint32_t* a, const uint32_t* b) {
    asm volatile("mma.sync.aligned.m16n8k16.row.col.f32.bf16.bf16.f32 "
                 "{%0,%1,%2,%3}, {%4,%5,%6,%7}, {%8,%9}, {%0,%1,%2,%3};"
                 : "+f"(c[0]), "+f"(c[1]), "+f"(c[2]), "+f"(c[3])
                 : "r"(a[0]), "r"(a[1]), "r"(a[2]), "r"(a[3]), "r"(b[0]), "r"(b[1]));
}
__device__ __forceinline__ void cp16(uint32_t saddr, const void* g) {
    asm volatile("cp.async.cg.shared.global [%0], [%1], 16;" :: "r"(saddr), "l"(g));
}
#define CP_COMMIT() asm volatile("cp.async.commit_group;" ::: "memory")
#define CP_WAIT0()  asm volatile("cp.async.wait_group 0;" ::: "memory")
#define CP_WAIT1()  asm volatile("cp.async.wait_group 1;" ::: "memory")

// Split a float pair into bf16x2 hi + lo words
__device__ __forceinline__ void split2w(float a, float b, uint32_t& h, uint32_t& l) {
    __nv_bfloat16 ha = __float2bfloat16(a), hb = __float2bfloat16(b);
    __nv_bfloat162 H; H.x = ha; H.y = hb;
    __nv_bfloat162 L;
    L.x = __float2bfloat16(a - __bfloat162float(ha));
    L.y = __float2bfloat16(b - __bfloat162float(hb));
    h = *(uint32_t*)&H; l = *(uint32_t*)&L;
}

// ---------------------------------------------------------------------------
// Conversion kernels
// ---------------------------------------------------------------------------
__global__ __launch_bounds__(256)
void split_fp32(const float* __restrict__ src, __nv_bfloat16* __restrict__ hi,
                __nv_bfloat16* __restrict__ lo, int n4)
{
    int i = blockIdx.x * blockDim.x + threadIdx.x;
    if (i >= n4) return;
    float4 v = ((const float4*)src)[i];
    uint32_t h0, l0, h1, l1;
    split2w(v.x, v.y, h0, l0);
    split2w(v.z, v.w, h1, l1);
    ((uint32_t*)hi)[i * 2] = h0; ((uint32_t*)hi)[i * 2 + 1] = h1;
    ((uint32_t*)lo)[i * 2] = l0; ((uint32_t*)lo)[i * 2 + 1] = l1;
}

// W[K=768, Ndim] row-major -> transposed split bf16 [Ndim, 768]
__global__ __launch_bounds__(256)
void transpose_split(const float* __restrict__ W, __nv_bfloat16* __restrict__ Th,
                     __nv_bfloat16* __restrict__ Tl, int Ndim)
{
    __shared__ float t[32][33];
    int tx = threadIdx.x & 31, ty = threadIdx.x >> 5;
    int n0 = blockIdx.x * 32, k0 = blockIdx.y * 32;
#pragma unroll
    for (int i = 0; i < 32; i += 8)
        t[ty + i][tx] = W[(size_t)(k0 + ty + i) * Ndim + n0 + tx];
    __syncthreads();
#pragma unroll
    for (int i = 0; i < 32; i += 8) {
        float v = t[tx][ty + i];
        __nv_bfloat16 h = __float2bfloat16(v);
        size_t o = (size_t)(n0 + ty + i) * Kd + k0 + tx;
        Th[o] = h;
        Tl[o] = __float2bfloat16(v - __bfloat162float(h));
    }
}

// qkv fp32 -> attention operands: Qh/Ql (pre-scaled), Kh/Kl, VTh/VTl (transposed)
__global__ __launch_bounds__(256)
void attn_prep()
{
    __shared__ float vs[128][101];
    const int tt = blockIdx.x;     // token tile 0..63 (global over 8192)
    const int h  = blockIdx.y;     // head
    const int tid = threadIdx.x;
    const int b = tt >> 3;
    const int bh = b * Hn + h;
    const int tloc = (tt & 7) * 128;
    const float* base = g_qkv + (size_t)tt * 128 * N3 + h * Dn;
    const float scale = rsqrtf((float)Dn);

    uint32_t* Qh2 = (uint32_t*)(g_Qh + ((size_t)bh * Tn + tloc) * Dn);
    uint32_t* Ql2 = (uint32_t*)(g_Ql + ((size_t)bh * Tn + tloc) * Dn);
    uint32_t* Kh2 = (uint32_t*)(g_Kh + ((size_t)bh * Tn + tloc) * Dn);
    uint32_t* Kl2 = (uint32_t*)(g_Kl + ((size_t)bh * Tn + tloc) * Dn);

    for (int i = tid; i < 128 * 24; i += 256) {
        int row = i / 24, j = i - row * 24;
        const float* p = base + (size_t)row * N3 + j * 4;
        float4 q = *(const float4*)(p);
        float4 k = *(const float4*)(p + Cn);
        float4 v = *(const float4*)(p + 2 * Cn);
        uint32_t h0, l0, h1, l1;
        split2w(q.x * scale, q.y * scale, h0, l0);
        split2w(q.z * scale, q.w * scale, h1, l1);
        int o = row * 48 + j * 2;
        Qh2[o] = h0; Qh2[o + 1] = h1; Ql2[o] = l0; Ql2[o + 1] = l1;
        split2w(k.x, k.y, h0, l0);
        split2w(k.z, k.w, h1, l1);
        Kh2[o] = h0; Kh2[o + 1] = h1; Kl2[o] = l0; Kl2[o + 1] = l1;
        vs[row][j * 4 + 0] = v.x; vs[row][j * 4 + 1] = v.y;
        vs[row][j * 4 + 2] = v.z; vs[row][j * 4 + 3] = v.w;
    }
    __syncthreads();
    for (int i = tid; i < 96 * 64; i += 256) {
        int d = i >> 6, tp = i & 63;
        uint32_t hh, ll;
        split2w(vs[2 * tp][d], vs[2 * tp + 1][d], hh, ll);
        size_t o = (((size_t)bh * Dn + d) * Tn + tloc) / 2 + tp;
        ((uint32_t*)g_VTh)[o] = hh;
        ((uint32_t*)g_VTl)[o] = ll;
    }
}

// ---------------------------------------------------------------------------
// Tensor-core GEMM via mma.sync (bf16 3-term split), 3-stage cp.async
// pipeline, BK=64, one __syncthreads per K-tile, TERM-MAJOR MMA ordering
// (16 independent MMAs between accumulator reuses).
// ---------------------------------------------------------------------------
#define ROWB 144
#define TILEB (128 * ROWB)
#define STAGEB (4 * TILEB)
#define GEMM_SMEM_DYN (3 * STAGEB)  // 221184 B

extern __shared__ float sm_dyn[];

__device__ __forceinline__ void gemm_issue_stage(
    const __nv_bfloat16* const* tp, uint32_t sdst, int kt, int tid)
{
#pragma unroll
    for (int i = 0; i < 16; i++) {
        int id = i * 256 + tid;
        int tile = id >> 10;
        int r = (id >> 3) & 127;
        int c = id & 7;
        const __nv_bfloat16* g = tp[tile] + (size_t)r * Kd + kt * 64 + c * 8;
        cp16(sdst + tile * TILEB + r * ROWB + c * 16, g);
    }
    CP_COMMIT();
}

__global__ __launch_bounds__(256, 1)
void tensor_gemm(const __nv_bfloat16* __restrict__ Ah, const __nv_bfloat16* __restrict__ Al,
                 const __nv_bfloat16* __restrict__ BTh, const __nv_bfloat16* __restrict__ BTl,
                 const float* __restrict__ bias, float* __restrict__ Cout, int Ndim)
{
    const int tid = threadIdx.x;
    const int wid = tid >> 5, lane = tid & 31;
    const int m0 = blockIdx.y * 128;
    const int n0 = blockIdx.x * 128;
    const int wm = (wid >> 2) * 64;
    const int wn = (wid & 3) * 32;

    const uint32_t sbase = smem_u32(sm_dyn);

    const __nv_bfloat16* tp[4] = {
        Ah  + (size_t)m0 * Kd, Al  + (size_t)m0 * Kd,
        BTh + (size_t)n0 * Kd, BTl + (size_t)n0 * Kd
    };

    float acc[4][4][4];
#pragma unroll
    for (int mf = 0; mf < 4; mf++)
#pragma unroll
        for (int nf = 0; nf < 4; nf++)
#pragma unroll
            for (int j = 0; j < 4; j++) acc[mf][nf][j] = 0.f;

    const int arow = wm + (lane & 15);
    const int akb  = (lane >> 4) << 3;
    const int brow = wn + (lane & 7) + ((lane >> 4) << 3);
    const int bkb  = ((lane >> 3) & 1) << 3;

    gemm_issue_stage(tp, sbase, 0, tid);
    gemm_issue_stage(tp, sbase + STAGEB, 1, tid);

    for (int kt = 0; kt < 12; kt++) {
        if (kt < 11) CP_WAIT1(); else CP_WAIT0();
        __syncthreads();

        if (kt + 2 < 12)
            gemm_issue_stage(tp, sbase + ((kt + 2) % 3) * STAGEB, kt + 2, tid);

        const uint32_t Ahb = sbase + (kt % 3) * STAGEB;
        const uint32_t Alb = Ahb + TILEB;
        const uint32_t Bhb = Ahb + 2 * TILEB;
        const uint32_t Blb = Ahb + 3 * TILEB;

#pragma unroll
        for (int kf = 0; kf < 4; kf++) {
            const int kb = kf * 16;
            uint32_t ah[4][4], al[4][4], bh[4][2], bl[4][2];
#pragma unroll
            for (int mf = 0; mf < 4; mf++) {
                uint32_t off = (uint32_t)(arow + mf * 16) * ROWB + (kb + akb) * 2;
                ldsm_x4(ah[mf], Ahb + off);
                ldsm_x4(al[mf], Alb + off);
            }
#pragma unroll
            for (int np = 0; np < 2; np++) {
                uint32_t off = (uint32_t)(brow + np * 16) * ROWB + (kb + bkb) * 2;
                uint32_t t4[4];
                ldsm_x4(t4, Bhb + off);
                bh[2 * np][0] = t4[0]; bh[2 * np][1] = t4[1];
                bh[2 * np + 1][0] = t4[2]; bh[2 * np + 1][1] = t4[3];
                ldsm_x4(t4, Blb + off);
                bl[2 * np][0] = t4[0]; bl[2 * np][1] = t4[1];
                bl[2 * np + 1][0] = t4[2]; bl[2 * np + 1][1] = t4[3];
            }
            // Term-major: 16 independent MMAs between accumulator reuses
#pragma unroll
            for (int mf = 0; mf < 4; mf++)
#pragma unroll
                for (int nf = 0; nf < 4; nf++)
                    mma_16816(acc[mf][nf], ah[mf], bh[nf]);
#pragma unroll
            for (int mf = 0; mf < 4; mf++)
#pragma unroll
                for (int nf = 0; nf < 4; nf++)
                    mma_16816(acc[mf][nf], ah[mf], bl[nf]);
#pragma unroll
            for (int mf = 0; mf < 4; mf++)
#pragma unroll
                for (int nf = 0; nf < 4; nf++)
                    mma_16816(acc[mf][nf], al[mf], bh[nf]);
        }
    }

    const int mrow = m0 + wm + (lane >> 2);
    const int ncol = n0 + wn + (lane & 3) * 2;
#pragma unroll
    for (int mf = 0; mf < 4; mf++)
#pragma unroll
        for (int nf = 0; nf < 4; nf++) {
            int r = mrow + mf * 16, c = ncol + nf * 8;
            float b0 = bias[c], b1 = bias[c + 1];
            *(float2*)(Cout + (size_t)r * Ndim + c) =
                make_float2(acc[mf][nf][0] + b0, acc[mf][nf][1] + b1);
            *(float2*)(Cout + (size_t)(r + 8) * Ndim + c) =
                make_float2(acc[mf][nf][2] + b0, acc[mf][nf][3] + b1);
        }
}

// ---------------------------------------------------------------------------
// Tensor-core flash attention, PIPELINED:
//   K double-buffered (2 stages), V single-buffered with staggered commits:
//     iter kt: wait K(kt) | issue K(kt+1) | S + softmax | wait V(kt) | PV |
//              sync | issue V(kt+1)
//   qt reversed (longest CTAs scheduled first).
// smem: Q 53248 + K 2x53248 + V 52224 = 211968 B
// ---------------------------------------------------------------------------
#define SQp 208
#define SVp 272
#define AOFF_QH 0
#define AOFF_QL (128 * SQp)
#define AOFF_K  (2 * 128 * SQp)
#define KSTGB   (2 * 128 * SQp)
#define AOFF_VH (AOFF_K + 2 * KSTGB)
#define AOFF_VL (AOFF_VH + 96 * SVp)
#define ATT_SMEM (AOFF_VL + 96 * SVp)   // 211968 B

__device__ __forceinline__ void att_load_K(uint32_t kbase, const __nv_bfloat16* kh,
                                           const __nv_bfloat16* kl, int tid)
{
    for (int i = tid; i < 128 * 12; i += 256) {
        int r = i / 12, c = i - r * 12;
        cp16(kbase + r * SQp + c * 16, kh + r * Dn + c * 8);
        cp16(kbase + 128 * SQp + r * SQp + c * 16, kl + r * Dn + c * 8);
    }
    CP_COMMIT();
}
__device__ __forceinline__ void att_load_V(uint32_t sb, const __nv_bfloat16* gVh,
                                           const __nv_bfloat16* gVl, int kt, int tid)
{
    for (int i = tid; i < 96 * 16; i += 256) {
        int d = i >> 4, c = i & 15;
        cp16(sb + AOFF_VH + d * SVp + c * 16, gVh + (size_t)d * Tn + kt * 128 + c * 8);
        cp16(sb + AOFF_VL + d * SVp + c * 16, gVl + (size_t)d * Tn + kt * 128 + c * 8);
    }
    CP_COMMIT();
}

__global__ __launch_bounds__(256, 1)
void attention_mma()
{
    const int tid = threadIdx.x, lane = tid & 31, w = tid >> 5;
    const int qt = gridDim.x - 1 - blockIdx.x;   // long CTAs first
    const int bh = blockIdx.y;
    const int b = bh >> 3, h = bh & 7;
    const uint32_t sb = smem_u32(sm_dyn);

    const __nv_bfloat16* gQh = g_Qh + ((size_t)bh * Tn + qt * 128) * Dn;
    const __nv_bfloat16* gQl = g_Ql + ((size_t)bh * Tn + qt * 128) * Dn;
    const __nv_bfloat16* gKh = g_Kh + (size_t)bh * Tn * Dn;
    const __nv_bfloat16* gKl = g_Kl + (size_t)bh * Tn * Dn;
    const __nv_bfloat16* gVh = g_VTh + (size_t)bh * Dn * Tn;
    const __nv_bfloat16* gVl = g_VTl + (size_t)bh * Dn * Tn;

    // Preamble: Q + K0 as one group, V0 as second group
    for (int i = tid; i < 128 * 12; i += 256) {
        int r = i / 12, c = i - r * 12;
        cp16(sb + AOFF_QH + r * SQp + c * 16, gQh + r * Dn + c * 8);
        cp16(sb + AOFF_QL + r * SQp + c * 16, gQl + r * Dn + c * 8);
        cp16(sb + AOFF_K + r * SQp + c * 16, gKh + r * Dn + c * 8);
        cp16(sb + AOFF_K + 128 * SQp + r * SQp + c * 16, gKl + r * Dn + c * 8);
    }
    CP_COMMIT();
    att_load_V(sb, gVh, gVl, 0, tid);

    float oacc[12][4];
#pragma unroll
    for (int i = 0; i < 12; i++)
#pragma unroll
        for (int j = 0; j < 4; j++) oacc[i][j] = 0.f;
    float m0 = -1e30f, m1 = -1e30f, l0 = 0.f, l1 = 0.f;

    for (int kt = 0; kt <= qt; kt++) {
        // wait K(kt) (+Q on first iter); V(kt) may still be in flight
        CP_WAIT1();
        __syncthreads();

        // prefetch K(kt+1) into the other stage (overlaps S + softmax + PV)
        if (kt < qt)
            att_load_K(sb + AOFF_K + ((kt + 1) & 1) * KSTGB,
                       gKh + (size_t)(kt + 1) * 128 * Dn,
                       gKl + (size_t)(kt + 1) * 128 * Dn, tid);

        const uint32_t Khb = sb + AOFF_K + (kt & 1) * KSTGB;
        const uint32_t Klb = Khb + 128 * SQp;

        // ---- S = Q K^T (3-term split) ----
        float sacc[16][4];
#pragma unroll
        for (int i = 0; i < 16; i++)
#pragma unroll
            for (int j = 0; j < 4; j++) sacc[i][j] = 0.f;

#pragma unroll
        for (int kf = 0; kf < 6; kf++) {
            uint32_t qoff = (uint32_t)(w * 16 + (lane & 15)) * SQp + kf * 32 + (lane >> 4) * 16;
            uint32_t ah[4], al[4];
            ldsm_x4(ah, sb + AOFF_QH + qoff);
            ldsm_x4(al, sb + AOFF_QL + qoff);
#pragma unroll
            for (int p = 0; p < 8; p++) {
                uint32_t koff = (uint32_t)(p * 16 + (lane & 15)) * SQp + kf * 32 + (lane >> 4) * 16;
                uint32_t kh4[4], kl4[4];
                ldsm_x4(kh4, Khb + koff);
                ldsm_x4(kl4, Klb + koff);
                uint32_t b0h[2] = {kh4[0], kh4[2]}, b1h[2] = {kh4[1], kh4[3]};
                uint32_t b0l[2] = {kl4[0], kl4[2]}, b1l[2] = {kl4[1], kl4[3]};
                // distance-2 dependent chains
                mma_16816(sacc[2 * p],     ah, b0h);
                mma_16816(sacc[2 * p + 1], ah, b1h);
                mma_16816(sacc[2 * p],     ah, b0l);
                mma_16816(sacc[2 * p + 1], ah, b1l);
                mma_16816(sacc[2 * p],     al, b0h);
                mma_16816(sacc[2 * p + 1], al, b1h);
            }
        }

        if (kt == qt) {
            const int lr0 = w * 16 + (lane >> 2), lr1 = lr0 + 8;
#pragma unroll
            for (int nf = 0; nf < 16; nf++) {
                int lc = nf * 8 + (lane & 3) * 2;
                if (lc     > lr0) sacc[nf][0] = -1e30f;
                if (lc + 1 > lr0) sacc[nf][1] = -1e30f;
                if (lc     > lr1) sacc[nf][2] = -1e30f;
                if (lc + 1 > lr1) sacc[nf][3] = -1e30f;
            }
        }

        // ---- online softmax ----
        float tm0 = -1e30f, tm1 = -1e30f;
#pragma unroll
        for (int nf = 0; nf < 16; nf++) {
            tm0 = fmaxf(tm0, fmaxf(sacc[nf][0], sacc[nf][1]));
            tm1 = fmaxf(tm1, fmaxf(sacc[nf][2], sacc[nf][3]));
        }
        tm0 = fmaxf(tm0, __shfl_xor_sync(0xffffffffu, tm0, 1));
        tm0 = fmaxf(tm0, __shfl_xor_sync(0xffffffffu, tm0, 2));
        tm1 = fmaxf(tm1, __shfl_xor_sync(0xffffffffu, tm1, 1));
        tm1 = fmaxf(tm1, __shfl_xor_sync(0xffffffffu, tm1, 2));
        float nm0 = fmaxf(m0, tm0), nm1 = fmaxf(m1, tm1);
        float c0 = __expf(m0 - nm0), c1 = __expf(m1 - nm1);
        m0 = nm0; m1 = nm1;
        float ts0 = 0.f, ts1 = 0.f;
#pragma unroll
        for (int nf = 0; nf < 16; nf++) {
            sacc[nf][0] = __expf(sacc[nf][0] - nm0);
            sacc[nf][1] = __expf(sacc[nf][1] - nm0);
            sacc[nf][2] = __expf(sacc[nf][2] - nm1);
            sacc[nf][3] = __expf(sacc[nf][3] - nm1);
            ts0 += sacc[nf][0] + sacc[nf][1];
            ts1 += sacc[nf][2] + sacc[nf][3];
        }
        ts0 += __shfl_xor_sync(0xffffffffu, ts0, 1);
        ts0 += __shfl_xor_sync(0xffffffffu, ts0, 2);
        ts1 += __shfl_xor_sync(0xffffffffu, ts1, 1);
        ts1 += __shfl_xor_sync(0xffffffffu, ts1, 2);
        l0 = l0 * c0 + ts0;
        l1 = l1 * c1 + ts1;
#pragma unroll
        for (int nf = 0; nf < 12; nf++) {
            oacc[nf][0] *= c0; oacc[nf][1] *= c0;
            oacc[nf][2] *= c1; oacc[nf][3] *= c1;
        }

        // wait V(kt): only K(kt+1) may remain in flight
        if (kt < qt) CP_WAIT1(); else CP_WAIT0();
        __syncthreads();

        // ---- O += P V (P from S accumulators, 3-term split) ----
#pragma unroll
        for (int t = 0; t < 8; t++) {
            uint32_t pah[4], pal[4];
            split2w(sacc[2 * t][0],     sacc[2 * t][1],     pah[0], pal[0]);
            split2w(sacc[2 * t][2],     sacc[2 * t][3],     pah[1], pal[1]);
            split2w(sacc[2 * t + 1][0], sacc[2 * t + 1][1], pah[2], pal[2]);
            split2w(sacc[2 * t + 1][2], sacc[2 * t + 1][3], pah[3], pal[3]);
#pragma unroll
            for (int dp = 0; dp < 6; dp++) {
                uint32_t voff = (uint32_t)(dp * 16 + (lane & 15)) * SVp + t * 32 + (lane >> 4) * 16;
                uint32_t vh4[4], vl4[4];
                ldsm_x4(vh4, sb + AOFF_VH + voff);
                ldsm_x4(vl4, sb + AOFF_VL + voff);
                uint32_t b0h[2] = {vh4[0], vh4[2]}, b1h[2] = {vh4[1], vh4[3]};
                uint32_t b0l[2] = {vl4[0], vl4[2]}, b1l[2] = {vl4[1], vl4[3]};
                mma_16816(oacc[2 * dp],     pah, b0h);
                mma_16816(oacc[2 * dp + 1], pah, b1h);
                mma_16816(oacc[2 * dp],     pah, b0l);
                mma_16816(oacc[2 * dp + 1], pah, b1l);
                mma_16816(oacc[2 * dp],     pal, b0h);
                mma_16816(oacc[2 * dp + 1], pal, b1h);
            }
        }

        // all warps done reading V(kt) -> safe to overwrite
        __syncthreads();
        if (kt < qt)
            att_load_V(sb, gVh, gVl, kt + 1, tid);
    }

    // ---- epilogue: normalize, write y split bf16 [B*T, C] ----
    const float i0 = 1.f / l0, i1 = 1.f / l1;
    const size_t row0 = (size_t)b * Tn + qt * 128 + w * 16 + (lane >> 2);
#pragma unroll
    for (int nf = 0; nf < 12; nf++) {
        int col = h * Dn + nf * 8 + (lane & 3) * 2;
        uint32_t hh, ll;
        split2w(oacc[nf][0] * i0, oacc[nf][1] * i0, hh, ll);
        *(uint32_t*)(g_yh + row0 * Cn + col) = hh;
        *(uint32_t*)(g_yl + row0 * Cn + col) = ll;
        split2w(oacc[nf][2] * i1, oacc[nf][3] * i1, hh, ll);
        *(uint32_t*)(g_yh + (row0 + 8) * Cn + col) = hh;
        *(uint32_t*)(g_yl + (row0 + 8) * Cn + col) = ll;
    }
}

// ---------------------------------------------------------------------------
// Launch pipeline
// ---------------------------------------------------------------------------
extern "C" void kernel_launch(void* const* d_in, const int* in_sizes, int n_in,
                              void* d_out, int out_size)
{
    const float* x      = (const float*)d_in[0];
    const float* W_attn = (const float*)d_in[1];
    const float* b_attn = (const float*)d_in[2];
    const float* W_proj = (const float*)d_in[3];
    const float* b_proj = (const float*)d_in[4];
    float* out = (float*)d_out;

    float* qkv;
    __nv_bfloat16 *xh, *xl, *yh, *yl, *wath, *watl, *wpth, *wptl;
    cudaGetSymbolAddress((void**)&qkv,  g_qkv);
    cudaGetSymbolAddress((void**)&xh,   g_xh);
    cudaGetSymbolAddress((void**)&xl,   g_xl);
    cudaGetSymbolAddress((void**)&yh,   g_yh);
    cudaGetSymbolAddress((void**)&yl,   g_yl);
    cudaGetSymbolAddress((void**)&wath, g_WaTh);
    cudaGetSymbolAddress((void**)&watl, g_WaTl);
    cudaGetSymbolAddress((void**)&wpth, g_WpTh);
    cudaGetSymbolAddress((void**)&wptl, g_WpTl);

    cudaFuncSetAttribute(tensor_gemm,
                         cudaFuncAttributeMaxDynamicSharedMemorySize, GEMM_SMEM_DYN);
    cudaFuncSetAttribute(attention_mma,
                         cudaFuncAttributeMaxDynamicSharedMemorySize, ATT_SMEM);

    const int n4x = (Mn * Cn) / 4;
    split_fp32<<<(n4x + 255) / 256, 256>>>(x, xh, xl, n4x);
    transpose_split<<<dim3(N3 / 32, Kd / 32), 256>>>(W_attn, wath, watl, N3);
    transpose_split<<<dim3(Cn / 32, Kd / 32), 256>>>(W_proj, wpth, wptl, Cn);

    // 1) qkv = x @ W_attn + b_attn   [8192, 2304]
    tensor_gemm<<<dim3(N3 / 128, Mn / 128), 256, GEMM_SMEM_DYN>>>(
        xh, xl, wath, watl, b_attn, qkv, N3);

    // 2) attention operand prep + pipelined flash attention
    attn_prep<<<dim3(Mn / 128, Hn), 256>>>();
    attention_mma<<<dim3(Tn / 128, Bn * Hn), 256, ATT_SMEM>>>();

    // 3) out = y @ W_proj + b_proj   [8192, 768]
    tensor_gemm<<<dim3(Cn / 128, Mn / 128), 256, GEMM_SMEM_DYN>>>(
        yh, yl, wpth, wptl, b_proj, out, Cn);
}